// round 1
// baseline (speedup 1.0000x reference)
#include <cuda_runtime.h>
#include <cstdint>

// ---------------- problem constants ----------------
#define BATCH   4
#define SEQL    2048
#define DM      1024
#define DI      2048            // d_inner
#define NH      64              // heads
#define HP      32              // headdim
#define DS      128             // d_state
#define DCONV   4
#define CONVD   2304            // DI + 2*DS
#define DPROJ   4416            // 2*DI + 2*DS + NH
#define NL      4
#define ROWS    (BATCH*SEQL)    // 8192
#define DT_OFF  (DI + CONVD)    // 4352

// ---------------- device scratch (no allocation allowed) ----------------
__device__ float g_h  [(size_t)ROWS * DM];     // residual stream
__device__ float g_hn [(size_t)ROWS * DM];     // rmsnorm'd input
__device__ float g_zx [(size_t)ROWS * DPROJ];  // in_proj output
__device__ float g_xbc[(size_t)ROWS * CONVD];  // conv+silu output (x|B|C)
__device__ float g_dt [(size_t)ROWS * NH];
__device__ float g_dA [(size_t)ROWS * NH];
__device__ float g_y  [(size_t)ROWS * DI];     // scan output / gated-normed

// ---------------- helpers ----------------
__device__ __forceinline__ float block_reduce_sum(float v) {
    __shared__ float red[32];
    int lane = threadIdx.x & 31, wid = threadIdx.x >> 5;
#pragma unroll
    for (int o = 16; o; o >>= 1) v += __shfl_xor_sync(0xffffffffu, v, o);
    if (lane == 0) red[wid] = v;
    __syncthreads();
    float t = (threadIdx.x < (blockDim.x >> 5)) ? red[threadIdx.x] : 0.f;
    if (wid == 0) {
#pragma unroll
        for (int o = 16; o; o >>= 1) t += __shfl_xor_sync(0xffffffffu, t, o);
        if (lane == 0) red[0] = t;
    }
    __syncthreads();
    return red[0];
}

__device__ __forceinline__ float silu_f(float v) {
    return v / (1.0f + expf(-v));
}

// ---------------- kernels ----------------
__global__ void copy_kernel(const float* __restrict__ src, float* __restrict__ dst, size_t n4) {
    size_t i = (size_t)blockIdx.x * blockDim.x + threadIdx.x;
    if (i < n4) ((float4*)dst)[i] = ((const float4*)src)[i];
}

// rmsnorm over last dim D (D = 1024): one block per row, 256 threads
__global__ void rmsnorm_kernel(const float* __restrict__ src, const float* __restrict__ w,
                               float* __restrict__ dst, int D) {
    int row = blockIdx.x;
    const float* s = src + (size_t)row * D;
    float*       d = dst + (size_t)row * D;
    float ss = 0.f;
    for (int i = threadIdx.x * 4; i < D; i += blockDim.x * 4) {
        float4 v = *(const float4*)(s + i);
        ss += v.x*v.x + v.y*v.y + v.z*v.z + v.w*v.w;
    }
    float tot = block_reduce_sum(ss);
    float scale = rsqrtf(tot / (float)D + 1e-5f);
    for (int i = threadIdx.x * 4; i < D; i += blockDim.x * 4) {
        float4 v = *(const float4*)(s + i);
        float4 wv = *(const float4*)(w + i);
        float4 o;
        o.x = v.x * scale * wv.x;  o.y = v.y * scale * wv.y;
        o.z = v.z * scale * wv.z;  o.w = v.w * scale * wv.w;
        *(float4*)(d + i) = o;
    }
}

// ---- fp32 SGEMM: C[M,N] = A[M,K] @ B[K,N] (+ Cadd) ; row-major everywhere ----
#define BM 128
#define BN 128
#define BKK 8
__global__ void __launch_bounds__(256)
sgemm_kernel(const float* __restrict__ A, const float* __restrict__ B,
             const float* __restrict__ Cadd, float* __restrict__ C,
             int M, int N, int K) {
    __shared__ float As[BKK][BM];
    __shared__ float Bs[BKK][BN + 4];
    int tid = threadIdx.x;
    int bx = blockIdx.x, by = blockIdx.y;
    int nBase = bx * BN;

    int rowA = tid >> 1;                 // 0..127
    int colA = (tid & 1) << 2;           // 0 or 4
    int rowB = tid >> 5;                 // 0..7
    int colB = (tid & 31) << 2;          // 0..124
    int tr = tid >> 4;                   // 0..15
    int tc = tid & 15;                   // 0..15

    const float* Ap = A + (size_t)(by * BM) * K;
    float acc[8][8];
#pragma unroll
    for (int i = 0; i < 8; i++)
#pragma unroll
        for (int j = 0; j < 8; j++) acc[i][j] = 0.f;

    for (int k0 = 0; k0 < K; k0 += BKK) {
        // A tile (M always a multiple of 128 here)
        float4 a4 = *(const float4*)(Ap + (size_t)rowA * K + k0 + colA);
        As[colA + 0][rowA] = a4.x;
        As[colA + 1][rowA] = a4.y;
        As[colA + 2][rowA] = a4.z;
        As[colA + 3][rowA] = a4.w;
        // B tile with N-guard (N % 4 == 0 so float4 never straddles the edge)
        float4 b4 = make_float4(0.f, 0.f, 0.f, 0.f);
        if (nBase + colB < N)
            b4 = *(const float4*)(B + (size_t)(k0 + rowB) * N + nBase + colB);
        *(float4*)&Bs[rowB][colB] = b4;
        __syncthreads();

#pragma unroll
        for (int kk = 0; kk < BKK; kk++) {
            float ra[8], rb[8];
#pragma unroll
            for (int i = 0; i < 8; i++) ra[i] = As[kk][tr * 8 + i];
#pragma unroll
            for (int j = 0; j < 8; j++) rb[j] = Bs[kk][tc * 8 + j];
#pragma unroll
            for (int i = 0; i < 8; i++)
#pragma unroll
                for (int j = 0; j < 8; j++) acc[i][j] += ra[i] * rb[j];
        }
        __syncthreads();
    }

#pragma unroll
    for (int i = 0; i < 8; i++) {
        size_t m = (size_t)by * BM + tr * 8 + i;
        float* crow = C + m * N;
        const float* arow = Cadd ? (Cadd + m * N) : nullptr;
#pragma unroll
        for (int j = 0; j < 8; j++) {
            int n = nBase + tc * 8 + j;
            if (n < N) {
                float v = acc[i][j];
                if (arow) v += arow[n];
                crow[n] = v;
            }
        }
    }
}

// causal depthwise conv1d (width 4) over xBC channels + SiLU
__global__ void conv_silu_kernel(const float* __restrict__ cw, const float* __restrict__ cb) {
    size_t idx = (size_t)blockIdx.x * blockDim.x + threadIdx.x;
    if (idx >= (size_t)ROWS * CONVD) return;
    int c = (int)(idx % CONVD);
    size_t bl = idx / CONVD;
    int l = (int)(bl % SEQL);
    size_t b = bl / SEQL;
    const float* col = g_zx + (b * SEQL) * (size_t)DPROJ + DI + c;
    float w0 = cw[c * 4 + 0], w1 = cw[c * 4 + 1], w2 = cw[c * 4 + 2], w3 = cw[c * 4 + 3];
    float acc = cb[c];
    if (l >= 3) acc += col[(size_t)(l - 3) * DPROJ] * w0;
    if (l >= 2) acc += col[(size_t)(l - 2) * DPROJ] * w1;
    if (l >= 1) acc += col[(size_t)(l - 1) * DPROJ] * w2;
    acc += col[(size_t)l * DPROJ] * w3;
    g_xbc[idx] = silu_f(acc);
}

// dt = softplus(dt_raw + dt_bias); dA = exp(dt * (-exp(A_log)))
__global__ void dt_kernel(const float* __restrict__ dtb, const float* __restrict__ Alog) {
    int idx = blockIdx.x * blockDim.x + threadIdx.x;
    if (idx >= ROWS * NH) return;
    int h = idx & (NH - 1);
    int bl = idx >> 6;
    float x = g_zx[(size_t)bl * DPROJ + DT_OFF + h] + dtb[h];
    float sp = (x > 20.f) ? x : log1pf(expf(x));
    g_dt[idx] = sp;
    g_dA[idx] = expf(sp * (-expf(Alog[h])));
}

// selective scan: one CTA per (b,h). 256 threads: p = tid>>3, n-chunk = (tid&7)*16
__global__ void __launch_bounds__(256) scan_kernel(const float* __restrict__ Dv) {
    int bh = blockIdx.x;
    int b = bh >> 6, h = bh & 63;
    int tid = threadIdx.x;
    int p = tid >> 3, sub = tid & 7, n0 = sub * 16;

    float s[16];
#pragma unroll
    for (int i = 0; i < 16; i++) s[i] = 0.f;

    float Dh = Dv[h];
    const float* xb  = g_xbc + (size_t)b * SEQL * CONVD;
    const float* pdt = g_dt  + (size_t)b * SEQL * NH + h;
    const float* pdA = g_dA  + (size_t)b * SEQL * NH + h;
    float*       yo  = g_y   + (size_t)b * SEQL * DI + h * HP + p;

    for (int t = 0; t < SEQL; t++) {
        const float* row = xb + (size_t)t * CONVD;
        float xv  = __ldg(row + h * HP + p);
        float dtv = __ldg(pdt + (size_t)t * NH);
        float dAv = __ldg(pdA + (size_t)t * NH);
        float Bv[16], Cv[16];
        const float4* Bp = (const float4*)(row + DI + n0);
        const float4* Cp = (const float4*)(row + DI + DS + n0);
#pragma unroll
        for (int j = 0; j < 4; j++) ((float4*)Bv)[j] = __ldg(Bp + j);
#pragma unroll
        for (int j = 0; j < 4; j++) ((float4*)Cv)[j] = __ldg(Cp + j);

        float dtx = dtv * xv;
        float acc = 0.f;
#pragma unroll
        for (int i = 0; i < 16; i++) {
            s[i] = s[i] * dAv + dtx * Bv[i];
            acc += s[i] * Cv[i];
        }
        acc += __shfl_xor_sync(0xffffffffu, acc, 1);
        acc += __shfl_xor_sync(0xffffffffu, acc, 2);
        acc += __shfl_xor_sync(0xffffffffu, acc, 4);
        if (sub == 0) yo[(size_t)t * DI] = acc + Dh * xv;
    }
}

// y = rmsnorm(y * silu(z)) * gw   (in place on g_y); z = first DI cols of g_zx
__global__ void gate_norm_kernel(const float* __restrict__ gw) {
    int row = blockIdx.x;
    float*       yr = g_y  + (size_t)row * DI;
    const float* zr = g_zx + (size_t)row * DPROJ;
    int base = threadIdx.x * 8;            // 256*8 = 2048
    float v[8];
    float ss = 0.f;
#pragma unroll
    for (int i = 0; i < 8; i++) {
        float yv = yr[base + i];
        float zv = zr[base + i];
        float g = yv * silu_f(zv);
        v[i] = g;
        ss += g * g;
    }
    float tot = block_reduce_sum(ss);
    float scale = rsqrtf(tot / (float)DI + 1e-5f);
#pragma unroll
    for (int i = 0; i < 8; i++) yr[base + i] = v[i] * scale * gw[base + i];
}

// ---------------- launch ----------------
extern "C" void kernel_launch(void* const* d_in, const int* in_sizes, int n_in,
                              void* d_out, int out_size) {
    const float* x        = (const float*)d_in[0];
    const float* W_in     = (const float*)d_in[1];
    const float* conv_w   = (const float*)d_in[2];
    const float* conv_b   = (const float*)d_in[3];
    const float* dt_bias  = (const float*)d_in[4];
    const float* A_log    = (const float*)d_in[5];
    const float* Dvec     = (const float*)d_in[6];
    const float* gate_w   = (const float*)d_in[7];
    const float* W_out    = (const float*)d_in[8];
    const float* block_w  = (const float*)d_in[9];
    const float* final_w  = (const float*)d_in[10];

    float *ph, *phn, *pzx, *py;
    cudaGetSymbolAddress((void**)&ph,  g_h);
    cudaGetSymbolAddress((void**)&phn, g_hn);
    cudaGetSymbolAddress((void**)&pzx, g_zx);
    cudaGetSymbolAddress((void**)&py,  g_y);

    // h = x
    {
        size_t n4 = (size_t)ROWS * DM / 4;
        copy_kernel<<<(unsigned)((n4 + 255) / 256), 256>>>(x, ph, n4);
    }

    for (int l = 0; l < NL; l++) {
        rmsnorm_kernel<<<ROWS, 256>>>(ph, block_w + (size_t)l * DM, phn, DM);

        dim3 g1((DPROJ + BN - 1) / BN, ROWS / BM);   // 35 x 64
        sgemm_kernel<<<g1, 256>>>(phn, W_in + (size_t)l * DM * DPROJ,
                                  nullptr, pzx, ROWS, DPROJ, DM);

        {
            size_t n = (size_t)ROWS * CONVD;
            conv_silu_kernel<<<(unsigned)((n + 255) / 256), 256>>>(
                conv_w + (size_t)l * CONVD * DCONV, conv_b + (size_t)l * CONVD);
        }

        dt_kernel<<<(ROWS * NH + 255) / 256, 256>>>(dt_bias + (size_t)l * NH,
                                                    A_log + (size_t)l * NH);

        scan_kernel<<<BATCH * NH, 256>>>(Dvec + (size_t)l * NH);

        gate_norm_kernel<<<ROWS, 256>>>(gate_w + (size_t)l * DI);

        dim3 g2((DM + BN - 1) / BN, ROWS / BM);      // 8 x 64
        sgemm_kernel<<<g2, 256>>>(py, W_out + (size_t)l * DI * DM,
                                  ph, ph, ROWS, DM, DI);
    }

    rmsnorm_kernel<<<ROWS, 256>>>(ph, final_w, (float*)d_out, DM);
}

// round 3
// speedup vs baseline: 1.4447x; 1.4447x over previous
#include <cuda_runtime.h>
#include <cuda_bf16.h>
#include <cstdint>

// ---------------- problem constants ----------------
#define BATCH   4
#define SEQL    2048
#define DM      1024
#define DI      2048
#define NH      64
#define HP      32
#define DS      128
#define DCONV   4
#define CONVD   2304            // DI + 2*DS
#define DPROJ   4416            // 2*DI + 2*DS + NH
#define NL      4
#define ROWS    (BATCH*SEQL)    // 8192
#define DT_OFF  (DI + CONVD)    // 4352
#define NPAD_IN 4480            // DPROJ padded to 128 multiple

// ---------------- device scratch (no allocation allowed) ----------------
__device__ float g_h  [(size_t)ROWS * DM];
__device__ float g_zx [(size_t)ROWS * DPROJ];
__device__ float g_xbc[(size_t)ROWS * CONVD];
__device__ float g_dt [(size_t)ROWS * NH];
__device__ float g_dA [(size_t)ROWS * NH];
__device__ float g_y  [(size_t)ROWS * DI];
// bf16 hi/lo GEMM operands
__device__ __nv_bfloat16 g_ah[(size_t)ROWS * DI];
__device__ __nv_bfloat16 g_al[(size_t)ROWS * DI];
__device__ __nv_bfloat16 g_bh[(size_t)NPAD_IN * 1024];
__device__ __nv_bfloat16 g_bl[(size_t)NPAD_IN * 1024];

// ---------------- small helpers ----------------
__device__ __forceinline__ float silu_f(float v) { return v / (1.0f + expf(-v)); }

__device__ __forceinline__ float block_reduce_sum(float v) {
    __shared__ float red[32];
    int lane = threadIdx.x & 31, wid = threadIdx.x >> 5;
#pragma unroll
    for (int o = 16; o; o >>= 1) v += __shfl_xor_sync(0xffffffffu, v, o);
    if (lane == 0) red[wid] = v;
    __syncthreads();
    float t = (threadIdx.x < (blockDim.x >> 5)) ? red[threadIdx.x] : 0.f;
    if (wid == 0) {
#pragma unroll
        for (int o = 16; o; o >>= 1) t += __shfl_xor_sync(0xffffffffu, t, o);
        if (lane == 0) red[0] = t;
    }
    __syncthreads();
    return red[0];
}

// ---------------- PTX wrappers (sm_100-baseline safe: cp.async/ldmatrix/mma.sync) ---
__device__ __forceinline__ uint32_t smem_u32(const void* p) {
    uint32_t a;
    asm("{ .reg .u64 t; cvta.to.shared.u64 t, %1; cvt.u32.u64 %0, t; }" : "=r"(a) : "l"(p));
    return a;
}
__device__ __forceinline__ void cp_async16(uint32_t dst, const void* src) {
    asm volatile("cp.async.cg.shared.global [%0], [%1], 16;" :: "r"(dst), "l"(src));
}
__device__ __forceinline__ void cp_commit() { asm volatile("cp.async.commit_group;" ::: "memory"); }
__device__ __forceinline__ void cp_wait0()  { asm volatile("cp.async.wait_group 0;" ::: "memory"); }
__device__ __forceinline__ void cp_wait1()  { asm volatile("cp.async.wait_group 1;" ::: "memory"); }

__device__ __forceinline__ void ldm_x4(uint32_t& r0, uint32_t& r1, uint32_t& r2, uint32_t& r3,
                                       uint32_t addr) {
    asm volatile("ldmatrix.sync.aligned.m8n8.x4.shared.b16 {%0,%1,%2,%3}, [%4];"
                 : "=r"(r0), "=r"(r1), "=r"(r2), "=r"(r3) : "r"(addr));
}
__device__ __forceinline__ void mma_bf16(float* c, const uint32_t* a, const uint32_t* b) {
    asm volatile("mma.sync.aligned.m16n8k16.row.col.f32.bf16.bf16.f32 "
                 "{%0,%1,%2,%3}, {%4,%5,%6,%7}, {%8,%9}, {%0,%1,%2,%3};"
                 : "+f"(c[0]), "+f"(c[1]), "+f"(c[2]), "+f"(c[3])
                 : "r"(a[0]), "r"(a[1]), "r"(a[2]), "r"(a[3]), "r"(b[0]), "r"(b[1]));
}

// ---------------- bf16 triple-pass GEMM: C[M,N] = A @ B^T (+Cadd) ----------------
// A(hi/lo): [M,K] bf16 row-major.  B(hi/lo): [Npad,K] bf16 row-major (pad rows zero).
// CTA tile 128x128, BK=32, 8 warps (4 along M x 2 along N), warp tile 32x64.
#define LDS 40                               // padded smem row stride (bf16 elems)
#define TILEB (128 * LDS * 2)                // bytes per operand tile (10240)
#define STAGEB (4 * TILEB)                   // Ah,Al,Bh,Bl
#define GEMM_SMEM (2 * STAGEB)               // 81920

__global__ void __launch_bounds__(256, 1)
gemm3_kernel(const __nv_bfloat16* __restrict__ Ah, const __nv_bfloat16* __restrict__ Al,
             const __nv_bfloat16* __restrict__ Bh, const __nv_bfloat16* __restrict__ Bl,
             const float* __restrict__ Cadd, float* __restrict__ C, int N, int K)
{
    extern __shared__ char smem[];
    const uint32_t sb = smem_u32(smem);
    const int tid = threadIdx.x;
    const int lane = tid & 31, wid = tid >> 5;
    const int wm = wid >> 1, wn = wid & 1;    // warp position: 4 x 2
    const size_t m0 = (size_t)blockIdx.y * 128;
    const size_t n0 = (size_t)blockIdx.x * 128;
    const int KC = K >> 5;                    // BK = 32

    float acc[2][8][4];
#pragma unroll
    for (int i = 0; i < 2; i++)
#pragma unroll
        for (int j = 0; j < 8; j++)
#pragma unroll
            for (int q = 0; q < 4; q++) acc[i][j][q] = 0.f;

    // per-thread cp.async chunk mapping: 2048 chunks of 16B per stage, 8 per thread
    // chunk i: tile t = i>>9, row r = (i>>2)&127, col chunk c = i&3
    const __nv_bfloat16* gbase[4] = { Ah, Al, Bh, Bl };

    // ldmatrix per-lane source offsets (elements within a tile)
    // A tiles: row m = lane%16, k-offset (lane/16)*8
    const int amr = lane & 15, akc = (lane >> 4) << 3;
    // B x4 over n16: n = (lane%8) + (lane>>4)*8, k-offset ((lane>>3)&1)*8
    const int bnr = (lane & 7) + ((lane >> 4) << 3), bkc = ((lane >> 3) & 1) << 3;

    auto load_stage = [&](int kc, int st) {
        uint32_t sbase = sb + st * STAGEB;
        size_t kOff = (size_t)kc << 5;
#pragma unroll
        for (int j = 0; j < 8; j++) {
            int i = tid + (j << 8);
            int t = i >> 9, r = (i >> 2) & 127, c = i & 3;
            size_t row = (t < 2) ? (m0 + r) : (n0 + r);
            const __nv_bfloat16* g = gbase[t] + row * (size_t)K + kOff + (c << 3);
            uint32_t d = sbase + (uint32_t)t * TILEB + (uint32_t)(r * LDS + (c << 3)) * 2;
            cp_async16(d, g);
        }
        cp_commit();
    };

    load_stage(0, 0);

    for (int kc = 0; kc < KC; kc++) {
        int st = kc & 1;
        if (kc + 1 < KC) { load_stage(kc + 1, st ^ 1); cp_wait1(); }
        else             { cp_wait0(); }
        __syncthreads();

        uint32_t sA = sb + st * STAGEB;
        uint32_t sAh = sA;
        uint32_t sAl = sA + TILEB;
        uint32_t sBh = sA + 2 * TILEB;
        uint32_t sBl = sA + 3 * TILEB;

#pragma unroll
        for (int kk = 0; kk < 2; kk++) {          // two k16 steps
            uint32_t ah[2][4], al[2][4];
#pragma unroll
            for (int mt = 0; mt < 2; mt++) {
                uint32_t off = (uint32_t)((wm * 32 + mt * 16 + amr) * LDS + kk * 16 + akc) * 2;
                ldm_x4(ah[mt][0], ah[mt][1], ah[mt][2], ah[mt][3], sAh + off);
                ldm_x4(al[mt][0], al[mt][1], al[mt][2], al[mt][3], sAl + off);
            }
            uint32_t bh[8][2], bl[8][2];
#pragma unroll
            for (int nt2 = 0; nt2 < 4; nt2++) {   // n16 groups
                uint32_t off = (uint32_t)((wn * 64 + nt2 * 16 + bnr) * LDS + kk * 16 + bkc) * 2;
                uint32_t r0, r1, r2, r3;
                ldm_x4(r0, r1, r2, r3, sBh + off);
                bh[nt2 * 2][0] = r0; bh[nt2 * 2][1] = r1;
                bh[nt2 * 2 + 1][0] = r2; bh[nt2 * 2 + 1][1] = r3;
                ldm_x4(r0, r1, r2, r3, sBl + off);
                bl[nt2 * 2][0] = r0; bl[nt2 * 2][1] = r1;
                bl[nt2 * 2 + 1][0] = r2; bl[nt2 * 2 + 1][1] = r3;
            }
#pragma unroll
            for (int mt = 0; mt < 2; mt++)
#pragma unroll
                for (int nt = 0; nt < 8; nt++) {
                    mma_bf16(acc[mt][nt], ah[mt], bh[nt]);
                    mma_bf16(acc[mt][nt], ah[mt], bl[nt]);
                    mma_bf16(acc[mt][nt], al[mt], bh[nt]);
                }
        }
        __syncthreads();
    }

    // epilogue: direct fp32 stores (+ optional Cadd)
    const int colb = (lane & 3) << 1;
    const int rowb = lane >> 2;
#pragma unroll
    for (int mt = 0; mt < 2; mt++) {
        size_t r0 = m0 + wm * 32 + mt * 16 + rowb;
#pragma unroll
        for (int half = 0; half < 2; half++) {
            size_t r = r0 + half * 8;
            float* crow = C + r * (size_t)N;
            const float* arow = Cadd ? Cadd + r * (size_t)N : nullptr;
#pragma unroll
            for (int nt = 0; nt < 8; nt++) {
                int col = (int)n0 + wn * 64 + nt * 8 + colb;
                if (col < N) {
                    float2 v;
                    v.x = acc[mt][nt][half * 2 + 0];
                    v.y = acc[mt][nt][half * 2 + 1];
                    if (arow) { v.x += arow[col]; v.y += arow[col + 1]; }
                    *(float2*)(crow + col) = v;
                }
            }
        }
    }
}

// ---------------- elementwise / norm kernels ----------------
__global__ void copy_kernel(const float* __restrict__ src, float* __restrict__ dst, size_t n4) {
    size_t i = (size_t)blockIdx.x * blockDim.x + threadIdx.x;
    if (i < n4) ((float4*)dst)[i] = ((const float4*)src)[i];
}

// rmsnorm -> fp32 (final norm only)
__global__ void rmsnorm_kernel(const float* __restrict__ src, const float* __restrict__ w,
                               float* __restrict__ dst, int D) {
    int row = blockIdx.x;
    const float* s = src + (size_t)row * D;
    float*       d = dst + (size_t)row * D;
    float ss = 0.f;
    for (int i = threadIdx.x * 4; i < D; i += blockDim.x * 4) {
        float4 v = *(const float4*)(s + i);
        ss += v.x * v.x + v.y * v.y + v.z * v.z + v.w * v.w;
    }
    float scale = rsqrtf(block_reduce_sum(ss) / (float)D + 1e-5f);
    for (int i = threadIdx.x * 4; i < D; i += blockDim.x * 4) {
        float4 v = *(const float4*)(s + i);
        float4 wv = *(const float4*)(w + i);
        float4 o;
        o.x = v.x * scale * wv.x; o.y = v.y * scale * wv.y;
        o.z = v.z * scale * wv.z; o.w = v.w * scale * wv.w;
        *(float4*)(d + i) = o;
    }
}

// rmsnorm -> bf16 hi/lo split (GEMM A operand)
__global__ void rmsnorm_split_kernel(const float* __restrict__ src, const float* __restrict__ w,
                                     __nv_bfloat16* __restrict__ hi, __nv_bfloat16* __restrict__ lo,
                                     int D) {
    int row = blockIdx.x;
    const float* s = src + (size_t)row * D;
    float ss = 0.f;
    for (int i = threadIdx.x * 4; i < D; i += blockDim.x * 4) {
        float4 v = *(const float4*)(s + i);
        ss += v.x * v.x + v.y * v.y + v.z * v.z + v.w * v.w;
    }
    float scale = rsqrtf(block_reduce_sum(ss) / (float)D + 1e-5f);
    for (int i = threadIdx.x * 4; i < D; i += blockDim.x * 4) {
        float4 v = *(const float4*)(s + i);
        float4 wv = *(const float4*)(w + i);
        float o[4] = { v.x * scale * wv.x, v.y * scale * wv.y,
                       v.z * scale * wv.z, v.w * scale * wv.w };
        __nv_bfloat16 h[4], l[4];
#pragma unroll
        for (int q = 0; q < 4; q++) {
            h[q] = __float2bfloat16(o[q]);
            l[q] = __float2bfloat16(o[q] - __bfloat162float(h[q]));
        }
        *(__nv_bfloat162*)(hi + (size_t)row * D + i)     = __nv_bfloat162(h[0], h[1]);
        *(__nv_bfloat162*)(hi + (size_t)row * D + i + 2) = __nv_bfloat162(h[2], h[3]);
        *(__nv_bfloat162*)(lo + (size_t)row * D + i)     = __nv_bfloat162(l[0], l[1]);
        *(__nv_bfloat162*)(lo + (size_t)row * D + i + 2) = __nv_bfloat162(l[2], l[3]);
    }
}

// W [K,N] fp32 -> transposed bf16 hi/lo [Npad,K] (pad rows zeroed)
__global__ void wsplit_kernel(const float* __restrict__ W,
                              __nv_bfloat16* __restrict__ Th, __nv_bfloat16* __restrict__ Tl,
                              int K, int N, int Npad) {
    __shared__ float tile[32][33];
    int nb = blockIdx.x * 32, kb = blockIdx.y * 32;
    int tx = threadIdx.x, ty = threadIdx.y;
#pragma unroll
    for (int j = 0; j < 4; j++) {
        int k = kb + ty + j * 8, n = nb + tx;
        tile[ty + j * 8][tx] = (n < N) ? W[(size_t)k * N + n] : 0.f;
    }
    __syncthreads();
#pragma unroll
    for (int j = 0; j < 4; j++) {
        int n = nb + ty + j * 8, k = kb + tx;
        float v = tile[tx][ty + j * 8];
        __nv_bfloat16 h = __float2bfloat16(v);
        Th[(size_t)n * K + k] = h;
        Tl[(size_t)n * K + k] = __float2bfloat16(v - __bfloat162float(h));
    }
}

// causal depthwise conv1d (width 4) + SiLU
__global__ void conv_silu_kernel(const float* __restrict__ cw, const float* __restrict__ cb) {
    size_t idx = (size_t)blockIdx.x * blockDim.x + threadIdx.x;
    if (idx >= (size_t)ROWS * CONVD) return;
    int c = (int)(idx % CONVD);
    size_t bl = idx / CONVD;
    int l = (int)(bl % SEQL);
    size_t b = bl / SEQL;
    const float* col = g_zx + (b * SEQL) * (size_t)DPROJ + DI + c;
    float w0 = cw[c * 4 + 0], w1 = cw[c * 4 + 1], w2 = cw[c * 4 + 2], w3 = cw[c * 4 + 3];
    float acc = cb[c];
    if (l >= 3) acc += col[(size_t)(l - 3) * DPROJ] * w0;
    if (l >= 2) acc += col[(size_t)(l - 2) * DPROJ] * w1;
    if (l >= 1) acc += col[(size_t)(l - 1) * DPROJ] * w2;
    acc += col[(size_t)l * DPROJ] * w3;
    g_xbc[idx] = silu_f(acc);
}

__global__ void dt_kernel(const float* __restrict__ dtb, const float* __restrict__ Alog) {
    int idx = blockIdx.x * blockDim.x + threadIdx.x;
    if (idx >= ROWS * NH) return;
    int h = idx & (NH - 1);
    int bl = idx >> 6;
    float x = g_zx[(size_t)bl * DPROJ + DT_OFF + h] + dtb[h];
    float sp = (x > 20.f) ? x : log1pf(expf(x));
    g_dt[idx] = sp;
    g_dA[idx] = expf(sp * (-expf(Alog[h])));
}

__global__ void __launch_bounds__(256) scan_kernel(const float* __restrict__ Dv) {
    int bh = blockIdx.x;
    int b = bh >> 6, h = bh & 63;
    int tid = threadIdx.x;
    int p = tid >> 3, sub = tid & 7, n0 = sub * 16;
    float s[16];
#pragma unroll
    for (int i = 0; i < 16; i++) s[i] = 0.f;
    float Dh = Dv[h];
    const float* xb  = g_xbc + (size_t)b * SEQL * CONVD;
    const float* pdt = g_dt  + (size_t)b * SEQL * NH + h;
    const float* pdA = g_dA  + (size_t)b * SEQL * NH + h;
    float*       yo  = g_y   + (size_t)b * SEQL * DI + h * HP + p;
    for (int t = 0; t < SEQL; t++) {
        const float* row = xb + (size_t)t * CONVD;
        float xv  = __ldg(row + h * HP + p);
        float dtv = __ldg(pdt + (size_t)t * NH);
        float dAv = __ldg(pdA + (size_t)t * NH);
        float Bv[16], Cv[16];
        const float4* Bp = (const float4*)(row + DI + n0);
        const float4* Cp = (const float4*)(row + DI + DS + n0);
#pragma unroll
        for (int j = 0; j < 4; j++) ((float4*)Bv)[j] = __ldg(Bp + j);
#pragma unroll
        for (int j = 0; j < 4; j++) ((float4*)Cv)[j] = __ldg(Cp + j);
        float dtx = dtv * xv;
        float acc = 0.f;
#pragma unroll
        for (int i = 0; i < 16; i++) {
            s[i] = s[i] * dAv + dtx * Bv[i];
            acc += s[i] * Cv[i];
        }
        acc += __shfl_xor_sync(0xffffffffu, acc, 1);
        acc += __shfl_xor_sync(0xffffffffu, acc, 2);
        acc += __shfl_xor_sync(0xffffffffu, acc, 4);
        if (sub == 0) yo[(size_t)t * DI] = acc + Dh * xv;
    }
}

// y' = rmsnorm(y * silu(z)) * gw -> bf16 hi/lo (A operand of out_proj)
__global__ void gate_norm_split_kernel(const float* __restrict__ gw,
                                       __nv_bfloat16* __restrict__ hi,
                                       __nv_bfloat16* __restrict__ lo) {
    int row = blockIdx.x;
    const float* yr = g_y  + (size_t)row * DI;
    const float* zr = g_zx + (size_t)row * DPROJ;
    int base = threadIdx.x * 8;
    float v[8];
    float ss = 0.f;
#pragma unroll
    for (int i = 0; i < 8; i++) {
        float g = yr[base + i] * silu_f(zr[base + i]);
        v[i] = g;
        ss += g * g;
    }
    float scale = rsqrtf(block_reduce_sum(ss) / (float)DI + 1e-5f);
    __nv_bfloat16 h[8], l[8];
#pragma unroll
    for (int i = 0; i < 8; i++) {
        float o = v[i] * scale * gw[base + i];
        h[i] = __float2bfloat16(o);
        l[i] = __float2bfloat16(o - __bfloat162float(h[i]));
    }
#pragma unroll
    for (int i = 0; i < 4; i++) {
        *(__nv_bfloat162*)(hi + (size_t)row * DI + base + i * 2) = __nv_bfloat162(h[i * 2], h[i * 2 + 1]);
        *(__nv_bfloat162*)(lo + (size_t)row * DI + base + i * 2) = __nv_bfloat162(l[i * 2], l[i * 2 + 1]);
    }
}

// ---------------- launch ----------------
extern "C" void kernel_launch(void* const* d_in, const int* in_sizes, int n_in,
                              void* d_out, int out_size) {
    const float* x        = (const float*)d_in[0];
    const float* W_in     = (const float*)d_in[1];
    const float* conv_w   = (const float*)d_in[2];
    const float* conv_b   = (const float*)d_in[3];
    const float* dt_bias  = (const float*)d_in[4];
    const float* A_log    = (const float*)d_in[5];
    const float* Dvec     = (const float*)d_in[6];
    const float* gate_w   = (const float*)d_in[7];
    const float* W_out    = (const float*)d_in[8];
    const float* block_w  = (const float*)d_in[9];
    const float* final_w  = (const float*)d_in[10];

    float *ph, *pzx, *py;
    __nv_bfloat16 *pah, *pal, *pbh, *pbl;
    cudaGetSymbolAddress((void**)&ph,  g_h);
    cudaGetSymbolAddress((void**)&pzx, g_zx);
    cudaGetSymbolAddress((void**)&py,  g_y);
    cudaGetSymbolAddress((void**)&pah, g_ah);
    cudaGetSymbolAddress((void**)&pal, g_al);
    cudaGetSymbolAddress((void**)&pbh, g_bh);
    cudaGetSymbolAddress((void**)&pbl, g_bl);

    cudaFuncSetAttribute(gemm3_kernel, cudaFuncAttributeMaxDynamicSharedMemorySize, GEMM_SMEM);

    {
        size_t n4 = (size_t)ROWS * DM / 4;
        copy_kernel<<<(unsigned)((n4 + 255) / 256), 256>>>(x, ph, n4);
    }

    for (int l = 0; l < NL; l++) {
        rmsnorm_split_kernel<<<ROWS, 256>>>(ph, block_w + (size_t)l * DM, pah, pal, DM);
        wsplit_kernel<<<dim3(NPAD_IN / 32, DM / 32), dim3(32, 8)>>>(
            W_in + (size_t)l * DM * DPROJ, pbh, pbl, DM, DPROJ, NPAD_IN);
        gemm3_kernel<<<dim3(NPAD_IN / 128, ROWS / 128), 256, GEMM_SMEM>>>(
            pah, pal, pbh, pbl, nullptr, pzx, DPROJ, DM);

        {
            size_t n = (size_t)ROWS * CONVD;
            conv_silu_kernel<<<(unsigned)((n + 255) / 256), 256>>>(
                conv_w + (size_t)l * CONVD * DCONV, conv_b + (size_t)l * CONVD);
        }
        dt_kernel<<<(ROWS * NH + 255) / 256, 256>>>(dt_bias + (size_t)l * NH,
                                                    A_log + (size_t)l * NH);
        scan_kernel<<<BATCH * NH, 256>>>(Dvec + (size_t)l * NH);
        gate_norm_split_kernel<<<ROWS, 256>>>(gate_w + (size_t)l * DI, pah, pal);

        wsplit_kernel<<<dim3(DM / 32, DI / 32), dim3(32, 8)>>>(
            W_out + (size_t)l * DI * DM, pbh, pbl, DI, DM, DM);
        gemm3_kernel<<<dim3(DM / 128, ROWS / 128), 256, GEMM_SMEM>>>(
            pah, pal, pbh, pbl, ph, ph, DM, DI);
    }

    rmsnorm_kernel<<<ROWS, 256>>>(ph, final_w, (float*)d_out, DM);
}

// round 4
// speedup vs baseline: 1.4645x; 1.0137x over previous
#include <cuda_runtime.h>
#include <cuda_bf16.h>
#include <cstdint>

// ---------------- problem constants ----------------
#define BATCH   4
#define SEQL    2048
#define DM      1024
#define DI      2048
#define NH      64
#define HP      32
#define DS      128
#define DCONV   4
#define CONVD   2304            // DI + 2*DS
#define DPROJ   4416            // 2*DI + 2*DS + NH
#define NL      4
#define ROWS    (BATCH*SEQL)    // 8192
#define DT_OFF  (DI + CONVD)    // 4352
#define NPAD_IN 4480            // DPROJ padded to 128 multiple

// ---------------- device scratch (no allocation allowed) ----------------
__device__ float g_h  [(size_t)ROWS * DM];
__device__ float g_zx [(size_t)ROWS * DPROJ];
__device__ float g_xbc[(size_t)ROWS * CONVD];
__device__ float2 g_dd[(size_t)ROWS * NH];     // (dt, dA) packed
__device__ float g_y  [(size_t)ROWS * DI];
// bf16 hi/lo GEMM operands
__device__ __nv_bfloat16 g_ah[(size_t)ROWS * DI];
__device__ __nv_bfloat16 g_al[(size_t)ROWS * DI];
__device__ __nv_bfloat16 g_bh[(size_t)NPAD_IN * 1024];
__device__ __nv_bfloat16 g_bl[(size_t)NPAD_IN * 1024];

// ---------------- small helpers ----------------
__device__ __forceinline__ float silu_f(float v) { return v / (1.0f + expf(-v)); }

__device__ __forceinline__ float block_reduce_sum(float v) {
    __shared__ float red[32];
    int lane = threadIdx.x & 31, wid = threadIdx.x >> 5;
#pragma unroll
    for (int o = 16; o; o >>= 1) v += __shfl_xor_sync(0xffffffffu, v, o);
    if (lane == 0) red[wid] = v;
    __syncthreads();
    float t = (threadIdx.x < (blockDim.x >> 5)) ? red[threadIdx.x] : 0.f;
    if (wid == 0) {
#pragma unroll
        for (int o = 16; o; o >>= 1) t += __shfl_xor_sync(0xffffffffu, t, o);
        if (lane == 0) red[0] = t;
    }
    __syncthreads();
    return red[0];
}

// ---------------- PTX wrappers (sm_100-baseline safe) ----------------
__device__ __forceinline__ uint32_t smem_u32(const void* p) {
    uint32_t a;
    asm("{ .reg .u64 t; cvta.to.shared.u64 t, %1; cvt.u32.u64 %0, t; }" : "=r"(a) : "l"(p));
    return a;
}
__device__ __forceinline__ void cp_async16(uint32_t dst, const void* src) {
    asm volatile("cp.async.cg.shared.global [%0], [%1], 16;" :: "r"(dst), "l"(src));
}
__device__ __forceinline__ void cp_commit() { asm volatile("cp.async.commit_group;" ::: "memory"); }
__device__ __forceinline__ void cp_wait0()  { asm volatile("cp.async.wait_group 0;" ::: "memory"); }
__device__ __forceinline__ void cp_wait1()  { asm volatile("cp.async.wait_group 1;" ::: "memory"); }

__device__ __forceinline__ void ldm_x4(uint32_t& r0, uint32_t& r1, uint32_t& r2, uint32_t& r3,
                                       uint32_t addr) {
    asm volatile("ldmatrix.sync.aligned.m8n8.x4.shared.b16 {%0,%1,%2,%3}, [%4];"
                 : "=r"(r0), "=r"(r1), "=r"(r2), "=r"(r3) : "r"(addr));
}
__device__ __forceinline__ void mma_bf16(float* c, const uint32_t* a, const uint32_t* b) {
    asm volatile("mma.sync.aligned.m16n8k16.row.col.f32.bf16.bf16.f32 "
                 "{%0,%1,%2,%3}, {%4,%5,%6,%7}, {%8,%9}, {%0,%1,%2,%3};"
                 : "+f"(c[0]), "+f"(c[1]), "+f"(c[2]), "+f"(c[3])
                 : "r"(a[0]), "r"(a[1]), "r"(a[2]), "r"(a[3]), "r"(b[0]), "r"(b[1]));
}

// ---------------- bf16 triple-pass GEMM (unchanged from R3) ----------------
#define LDS 40
#define TILEB (128 * LDS * 2)
#define STAGEB (4 * TILEB)
#define GEMM_SMEM (2 * STAGEB)

__global__ void __launch_bounds__(256, 1)
gemm3_kernel(const __nv_bfloat16* __restrict__ Ah, const __nv_bfloat16* __restrict__ Al,
             const __nv_bfloat16* __restrict__ Bh, const __nv_bfloat16* __restrict__ Bl,
             const float* __restrict__ Cadd, float* __restrict__ C, int N, int K)
{
    extern __shared__ char smem[];
    const uint32_t sb = smem_u32(smem);
    const int tid = threadIdx.x;
    const int lane = tid & 31, wid = tid >> 5;
    const int wm = wid >> 1, wn = wid & 1;
    const size_t m0 = (size_t)blockIdx.y * 128;
    const size_t n0 = (size_t)blockIdx.x * 128;
    const int KC = K >> 5;

    float acc[2][8][4];
#pragma unroll
    for (int i = 0; i < 2; i++)
#pragma unroll
        for (int j = 0; j < 8; j++)
#pragma unroll
            for (int q = 0; q < 4; q++) acc[i][j][q] = 0.f;

    const __nv_bfloat16* gbase[4] = { Ah, Al, Bh, Bl };
    const int amr = lane & 15, akc = (lane >> 4) << 3;
    const int bnr = (lane & 7) + ((lane >> 4) << 3), bkc = ((lane >> 3) & 1) << 3;

    auto load_stage = [&](int kc, int st) {
        uint32_t sbase = sb + st * STAGEB;
        size_t kOff = (size_t)kc << 5;
#pragma unroll
        for (int j = 0; j < 8; j++) {
            int i = tid + (j << 8);
            int t = i >> 9, r = (i >> 2) & 127, c = i & 3;
            size_t row = (t < 2) ? (m0 + r) : (n0 + r);
            const __nv_bfloat16* g = gbase[t] + row * (size_t)K + kOff + (c << 3);
            uint32_t d = sb + st * STAGEB + (uint32_t)t * TILEB + (uint32_t)(r * LDS + (c << 3)) * 2;
            (void)sbase;
            cp_async16(d, g);
        }
        cp_commit();
    };

    load_stage(0, 0);

    for (int kc = 0; kc < KC; kc++) {
        int st = kc & 1;
        if (kc + 1 < KC) { load_stage(kc + 1, st ^ 1); cp_wait1(); }
        else             { cp_wait0(); }
        __syncthreads();

        uint32_t sA = sb + st * STAGEB;
        uint32_t sAh = sA;
        uint32_t sAl = sA + TILEB;
        uint32_t sBh = sA + 2 * TILEB;
        uint32_t sBl = sA + 3 * TILEB;

#pragma unroll
        for (int kk = 0; kk < 2; kk++) {
            uint32_t ah[2][4], al[2][4];
#pragma unroll
            for (int mt = 0; mt < 2; mt++) {
                uint32_t off = (uint32_t)((wm * 32 + mt * 16 + amr) * LDS + kk * 16 + akc) * 2;
                ldm_x4(ah[mt][0], ah[mt][1], ah[mt][2], ah[mt][3], sAh + off);
                ldm_x4(al[mt][0], al[mt][1], al[mt][2], al[mt][3], sAl + off);
            }
            uint32_t bh[8][2], bl[8][2];
#pragma unroll
            for (int nt2 = 0; nt2 < 4; nt2++) {
                uint32_t off = (uint32_t)((wn * 64 + nt2 * 16 + bnr) * LDS + kk * 16 + bkc) * 2;
                uint32_t r0, r1, r2, r3;
                ldm_x4(r0, r1, r2, r3, sBh + off);
                bh[nt2 * 2][0] = r0; bh[nt2 * 2][1] = r1;
                bh[nt2 * 2 + 1][0] = r2; bh[nt2 * 2 + 1][1] = r3;
                ldm_x4(r0, r1, r2, r3, sBl + off);
                bl[nt2 * 2][0] = r0; bl[nt2 * 2][1] = r1;
                bl[nt2 * 2 + 1][0] = r2; bl[nt2 * 2 + 1][1] = r3;
            }
#pragma unroll
            for (int mt = 0; mt < 2; mt++)
#pragma unroll
                for (int nt = 0; nt < 8; nt++) {
                    mma_bf16(acc[mt][nt], ah[mt], bh[nt]);
                    mma_bf16(acc[mt][nt], ah[mt], bl[nt]);
                    mma_bf16(acc[mt][nt], al[mt], bh[nt]);
                }
        }
        __syncthreads();
    }

    const int colb = (lane & 3) << 1;
    const int rowb = lane >> 2;
#pragma unroll
    for (int mt = 0; mt < 2; mt++) {
        size_t r0 = m0 + wm * 32 + mt * 16 + rowb;
#pragma unroll
        for (int half = 0; half < 2; half++) {
            size_t r = r0 + half * 8;
            float* crow = C + r * (size_t)N;
            const float* arow = Cadd ? Cadd + r * (size_t)N : nullptr;
#pragma unroll
            for (int nt = 0; nt < 8; nt++) {
                int col = (int)n0 + wn * 64 + nt * 8 + colb;
                if (col < N) {
                    float2 v;
                    v.x = acc[mt][nt][half * 2 + 0];
                    v.y = acc[mt][nt][half * 2 + 1];
                    if (arow) { v.x += arow[col]; v.y += arow[col + 1]; }
                    *(float2*)(crow + col) = v;
                }
            }
        }
    }
}

// ---------------- elementwise / norm kernels ----------------
__global__ void copy_kernel(const float* __restrict__ src, float* __restrict__ dst, size_t n4) {
    size_t i = (size_t)blockIdx.x * blockDim.x + threadIdx.x;
    if (i < n4) ((float4*)dst)[i] = ((const float4*)src)[i];
}

__global__ void rmsnorm_kernel(const float* __restrict__ src, const float* __restrict__ w,
                               float* __restrict__ dst, int D) {
    int row = blockIdx.x;
    const float* s = src + (size_t)row * D;
    float*       d = dst + (size_t)row * D;
    float ss = 0.f;
    for (int i = threadIdx.x * 4; i < D; i += blockDim.x * 4) {
        float4 v = *(const float4*)(s + i);
        ss += v.x * v.x + v.y * v.y + v.z * v.z + v.w * v.w;
    }
    float scale = rsqrtf(block_reduce_sum(ss) / (float)D + 1e-5f);
    for (int i = threadIdx.x * 4; i < D; i += blockDim.x * 4) {
        float4 v = *(const float4*)(s + i);
        float4 wv = *(const float4*)(w + i);
        float4 o;
        o.x = v.x * scale * wv.x; o.y = v.y * scale * wv.y;
        o.z = v.z * scale * wv.z; o.w = v.w * scale * wv.w;
        *(float4*)(d + i) = o;
    }
}

__global__ void rmsnorm_split_kernel(const float* __restrict__ src, const float* __restrict__ w,
                                     __nv_bfloat16* __restrict__ hi, __nv_bfloat16* __restrict__ lo,
                                     int D) {
    int row = blockIdx.x;
    const float* s = src + (size_t)row * D;
    float ss = 0.f;
    for (int i = threadIdx.x * 4; i < D; i += blockDim.x * 4) {
        float4 v = *(const float4*)(s + i);
        ss += v.x * v.x + v.y * v.y + v.z * v.z + v.w * v.w;
    }
    float scale = rsqrtf(block_reduce_sum(ss) / (float)D + 1e-5f);
    for (int i = threadIdx.x * 4; i < D; i += blockDim.x * 4) {
        float4 v = *(const float4*)(s + i);
        float4 wv = *(const float4*)(w + i);
        float o[4] = { v.x * scale * wv.x, v.y * scale * wv.y,
                       v.z * scale * wv.z, v.w * scale * wv.w };
        __nv_bfloat16 h[4], l[4];
#pragma unroll
        for (int q = 0; q < 4; q++) {
            h[q] = __float2bfloat16(o[q]);
            l[q] = __float2bfloat16(o[q] - __bfloat162float(h[q]));
        }
        *(__nv_bfloat162*)(hi + (size_t)row * D + i)     = __nv_bfloat162(h[0], h[1]);
        *(__nv_bfloat162*)(hi + (size_t)row * D + i + 2) = __nv_bfloat162(h[2], h[3]);
        *(__nv_bfloat162*)(lo + (size_t)row * D + i)     = __nv_bfloat162(l[0], l[1]);
        *(__nv_bfloat162*)(lo + (size_t)row * D + i + 2) = __nv_bfloat162(l[2], l[3]);
    }
}

__global__ void wsplit_kernel(const float* __restrict__ W,
                              __nv_bfloat16* __restrict__ Th, __nv_bfloat16* __restrict__ Tl,
                              int K, int N, int Npad) {
    __shared__ float tile[32][33];
    int nb = blockIdx.x * 32, kb = blockIdx.y * 32;
    int tx = threadIdx.x, ty = threadIdx.y;
#pragma unroll
    for (int j = 0; j < 4; j++) {
        int k = kb + ty + j * 8, n = nb + tx;
        tile[ty + j * 8][tx] = (n < N) ? W[(size_t)k * N + n] : 0.f;
    }
    __syncthreads();
#pragma unroll
    for (int j = 0; j < 4; j++) {
        int n = nb + ty + j * 8, k = kb + tx;
        float v = tile[tx][ty + j * 8];
        __nv_bfloat16 h = __float2bfloat16(v);
        Th[(size_t)n * K + k] = h;
        Tl[(size_t)n * K + k] = __float2bfloat16(v - __bfloat162float(h));
    }
}

__global__ void conv_silu_kernel(const float* __restrict__ cw, const float* __restrict__ cb) {
    size_t idx = (size_t)blockIdx.x * blockDim.x + threadIdx.x;
    if (idx >= (size_t)ROWS * CONVD) return;
    int c = (int)(idx % CONVD);
    size_t bl = idx / CONVD;
    int l = (int)(bl % SEQL);
    size_t b = bl / SEQL;
    const float* col = g_zx + (b * SEQL) * (size_t)DPROJ + DI + c;
    float w0 = cw[c * 4 + 0], w1 = cw[c * 4 + 1], w2 = cw[c * 4 + 2], w3 = cw[c * 4 + 3];
    float acc = cb[c];
    if (l >= 3) acc += col[(size_t)(l - 3) * DPROJ] * w0;
    if (l >= 2) acc += col[(size_t)(l - 2) * DPROJ] * w1;
    if (l >= 1) acc += col[(size_t)(l - 1) * DPROJ] * w2;
    acc += col[(size_t)l * DPROJ] * w3;
    g_xbc[idx] = silu_f(acc);
}

// dt = softplus(raw + bias); dA = exp(dt*A). packed as float2
__global__ void dt_kernel(const float* __restrict__ dtb, const float* __restrict__ Alog) {
    int idx = blockIdx.x * blockDim.x + threadIdx.x;
    if (idx >= ROWS * NH) return;
    int h = idx & (NH - 1);
    int bl = idx >> 6;
    float x = g_zx[(size_t)bl * DPROJ + DT_OFF + h] + dtb[h];
    float sp = (x > 20.f) ? x : log1pf(expf(x));
    g_dd[idx] = make_float2(sp, expf(sp * (-expf(Alog[h]))));
}

// ---------------- software-pipelined selective scan ----------------
// one CTA per (b,h); 256 threads: p = tid>>3 (headdim), sub = tid&7 (16-state chunk)
__global__ void __launch_bounds__(256) scan_kernel(const float* __restrict__ Dv) {
    int bh = blockIdx.x;
    int b = bh >> 6, h = bh & 63;
    int tid = threadIdx.x;
    int p = tid >> 3, sub = tid & 7, n0 = sub * 16;

    float s[16];
#pragma unroll
    for (int i = 0; i < 16; i++) s[i] = 0.f;

    float Dh = Dv[h];
    const float*  xb  = g_xbc + (size_t)b * SEQL * CONVD;
    const float2* pdd = g_dd  + (size_t)b * SEQL * NH + h;
    float*        yo  = g_y   + (size_t)b * SEQL * DI + h * HP + p;

    float B0[16], C0[16], x0; float2 d0;
    float B1[16], C1[16], x1; float2 d1;

#define SCAN_LOAD(Bv, Cv, xv, dd, t)                                            \
    {                                                                           \
        const float* row_ = xb + (size_t)(t) * CONVD;                           \
        const float4* Bp_ = (const float4*)(row_ + DI + n0);                    \
        const float4* Cp_ = (const float4*)(row_ + DI + DS + n0);               \
        ((float4*)(Bv))[0] = __ldg(Bp_ + 0); ((float4*)(Bv))[1] = __ldg(Bp_ + 1);\
        ((float4*)(Bv))[2] = __ldg(Bp_ + 2); ((float4*)(Bv))[3] = __ldg(Bp_ + 3);\
        ((float4*)(Cv))[0] = __ldg(Cp_ + 0); ((float4*)(Cv))[1] = __ldg(Cp_ + 1);\
        ((float4*)(Cv))[2] = __ldg(Cp_ + 2); ((float4*)(Cv))[3] = __ldg(Cp_ + 3);\
        xv = __ldg(row_ + h * HP + p);                                          \
        dd = __ldg(pdd + (size_t)(t) * NH);                                     \
    }

#define SCAN_STEP(Bv, Cv, xv, dd, t)                                            \
    {                                                                           \
        float dtx_ = dd.x * xv;                                                 \
        float a0_ = 0.f, a1_ = 0.f;                                             \
        _Pragma("unroll")                                                       \
        for (int i = 0; i < 16; i += 2) {                                       \
            s[i]   = fmaf(s[i],   dd.y, dtx_ * (Bv)[i]);                        \
            s[i+1] = fmaf(s[i+1], dd.y, dtx_ * (Bv)[i+1]);                      \
            a0_ = fmaf(s[i],   (Cv)[i],   a0_);                                 \
            a1_ = fmaf(s[i+1], (Cv)[i+1], a1_);                                 \
        }                                                                       \
        float acc_ = a0_ + a1_;                                                 \
        acc_ += __shfl_xor_sync(0xffffffffu, acc_, 1);                          \
        acc_ += __shfl_xor_sync(0xffffffffu, acc_, 2);                          \
        acc_ += __shfl_xor_sync(0xffffffffu, acc_, 4);                          \
        if (sub == 0) yo[(size_t)(t) * DI] = fmaf(Dh, xv, acc_);                \
    }

    SCAN_LOAD(B0, C0, x0, d0, 0);
    SCAN_LOAD(B1, C1, x1, d1, 1);

#pragma unroll 1
    for (int t = 0; t < SEQL; t += 2) {
        SCAN_STEP(B0, C0, x0, d0, t);
        if (t + 2 < SEQL) SCAN_LOAD(B0, C0, x0, d0, t + 2);
        SCAN_STEP(B1, C1, x1, d1, t + 1);
        if (t + 3 < SEQL) SCAN_LOAD(B1, C1, x1, d1, t + 3);
    }
#undef SCAN_LOAD
#undef SCAN_STEP
}

// y' = rmsnorm(y * silu(z)) * gw -> bf16 hi/lo (A operand of out_proj)
__global__ void gate_norm_split_kernel(const float* __restrict__ gw,
                                       __nv_bfloat16* __restrict__ hi,
                                       __nv_bfloat16* __restrict__ lo) {
    int row = blockIdx.x;
    const float* yr = g_y  + (size_t)row * DI;
    const float* zr = g_zx + (size_t)row * DPROJ;
    int base = threadIdx.x * 8;
    float v[8];
    float ss = 0.f;
#pragma unroll
    for (int i = 0; i < 8; i++) {
        float g = yr[base + i] * silu_f(zr[base + i]);
        v[i] = g;
        ss += g * g;
    }
    float scale = rsqrtf(block_reduce_sum(ss) / (float)DI + 1e-5f);
    __nv_bfloat16 h[8], l[8];
#pragma unroll
    for (int i = 0; i < 8; i++) {
        float o = v[i] * scale * gw[base + i];
        h[i] = __float2bfloat16(o);
        l[i] = __float2bfloat16(o - __bfloat162float(h[i]));
    }
#pragma unroll
    for (int i = 0; i < 4; i++) {
        *(__nv_bfloat162*)(hi + (size_t)row * DI + base + i * 2) = __nv_bfloat162(h[i * 2], h[i * 2 + 1]);
        *(__nv_bfloat162*)(lo + (size_t)row * DI + base + i * 2) = __nv_bfloat162(l[i * 2], l[i * 2 + 1]);
    }
}

// ---------------- launch ----------------
extern "C" void kernel_launch(void* const* d_in, const int* in_sizes, int n_in,
                              void* d_out, int out_size) {
    const float* x        = (const float*)d_in[0];
    const float* W_in     = (const float*)d_in[1];
    const float* conv_w   = (const float*)d_in[2];
    const float* conv_b   = (const float*)d_in[3];
    const float* dt_bias  = (const float*)d_in[4];
    const float* A_log    = (const float*)d_in[5];
    const float* Dvec     = (const float*)d_in[6];
    const float* gate_w   = (const float*)d_in[7];
    const float* W_out    = (const float*)d_in[8];
    const float* block_w  = (const float*)d_in[9];
    const float* final_w  = (const float*)d_in[10];

    float *ph, *pzx, *py;
    __nv_bfloat16 *pah, *pal, *pbh, *pbl;
    cudaGetSymbolAddress((void**)&ph,  g_h);
    cudaGetSymbolAddress((void**)&pzx, g_zx);
    cudaGetSymbolAddress((void**)&py,  g_y);
    cudaGetSymbolAddress((void**)&pah, g_ah);
    cudaGetSymbolAddress((void**)&pal, g_al);
    cudaGetSymbolAddress((void**)&pbh, g_bh);
    cudaGetSymbolAddress((void**)&pbl, g_bl);

    cudaFuncSetAttribute(gemm3_kernel, cudaFuncAttributeMaxDynamicSharedMemorySize, GEMM_SMEM);

    {
        size_t n4 = (size_t)ROWS * DM / 4;
        copy_kernel<<<(unsigned)((n4 + 255) / 256), 256>>>(x, ph, n4);
    }

    for (int l = 0; l < NL; l++) {
        rmsnorm_split_kernel<<<ROWS, 256>>>(ph, block_w + (size_t)l * DM, pah, pal, DM);
        wsplit_kernel<<<dim3(NPAD_IN / 32, DM / 32), dim3(32, 8)>>>(
            W_in + (size_t)l * DM * DPROJ, pbh, pbl, DM, DPROJ, NPAD_IN);
        gemm3_kernel<<<dim3(NPAD_IN / 128, ROWS / 128), 256, GEMM_SMEM>>>(
            pah, pal, pbh, pbl, nullptr, pzx, DPROJ, DM);

        {
            size_t n = (size_t)ROWS * CONVD;
            conv_silu_kernel<<<(unsigned)((n + 255) / 256), 256>>>(
                conv_w + (size_t)l * CONVD * DCONV, conv_b + (size_t)l * CONVD);
        }
        dt_kernel<<<(ROWS * NH + 255) / 256, 256>>>(dt_bias + (size_t)l * NH,
                                                    A_log + (size_t)l * NH);
        scan_kernel<<<BATCH * NH, 256>>>(Dvec + (size_t)l * NH);
        gate_norm_split_kernel<<<ROWS, 256>>>(gate_w + (size_t)l * DI, pah, pal);

        wsplit_kernel<<<dim3(DM / 32, DI / 32), dim3(32, 8)>>>(
            W_out + (size_t)l * DI * DM, pbh, pbl, DI, DM, DM);
        gemm3_kernel<<<dim3(DM / 128, ROWS / 128), 256, GEMM_SMEM>>>(
            pah, pal, pbh, pbl, ph, ph, DM, DI);
    }

    rmsnorm_kernel<<<ROWS, 256>>>(ph, final_w, (float*)d_out, DM);
}

// round 6
// speedup vs baseline: 1.4819x; 1.0119x over previous
#include <cuda_runtime.h>
#include <cuda_bf16.h>
#include <cstdint>

// ---------------- problem constants ----------------
#define BATCH   4
#define SEQL    2048
#define DM      1024
#define DI      2048
#define NH      64
#define HP      32
#define DS      128
#define DCONV   4
#define CONVD   2304            // DI + 2*DS
#define DPROJ   4416            // 2*DI + 2*DS + NH
#define NL      4
#define ROWS    (BATCH*SEQL)    // 8192
#define DT_OFF  (DI + CONVD)    // 4352
#define NPAD_IN 4480            // DPROJ padded to 128 multiple

// ---------------- device scratch (no allocation allowed) ----------------
__device__ float g_h  [(size_t)ROWS * DM];
__device__ float g_zx [(size_t)ROWS * DPROJ];
__device__ float g_xbc[(size_t)ROWS * CONVD];
__device__ float2 g_dd[(size_t)ROWS * NH];     // (dt, dA) packed
__device__ float g_y  [(size_t)ROWS * DI];
// bf16 hi/lo GEMM operands
__device__ __nv_bfloat16 g_ah[(size_t)ROWS * DI];
__device__ __nv_bfloat16 g_al[(size_t)ROWS * DI];
__device__ __nv_bfloat16 g_bh[(size_t)NPAD_IN * 1024];
__device__ __nv_bfloat16 g_bl[(size_t)NPAD_IN * 1024];

// ---------------- small helpers ----------------
__device__ __forceinline__ float silu_f(float v) { return v / (1.0f + expf(-v)); }

__device__ __forceinline__ float block_reduce_sum(float v) {
    __shared__ float red[32];
    int lane = threadIdx.x & 31, wid = threadIdx.x >> 5;
#pragma unroll
    for (int o = 16; o; o >>= 1) v += __shfl_xor_sync(0xffffffffu, v, o);
    if (lane == 0) red[wid] = v;
    __syncthreads();
    float t = (threadIdx.x < (blockDim.x >> 5)) ? red[threadIdx.x] : 0.f;
    if (wid == 0) {
#pragma unroll
        for (int o = 16; o; o >>= 1) t += __shfl_xor_sync(0xffffffffu, t, o);
        if (lane == 0) red[0] = t;
    }
    __syncthreads();
    return red[0];
}

// ---------------- PTX wrappers (sm_100-baseline safe) ----------------
__device__ __forceinline__ uint32_t smem_u32(const void* p) {
    uint32_t a;
    asm("{ .reg .u64 t; cvta.to.shared.u64 t, %1; cvt.u32.u64 %0, t; }" : "=r"(a) : "l"(p));
    return a;
}
__device__ __forceinline__ void cp_async16(uint32_t dst, const void* src) {
    asm volatile("cp.async.cg.shared.global [%0], [%1], 16;" :: "r"(dst), "l"(src));
}
__device__ __forceinline__ void cp_async8(uint32_t dst, const void* src) {
    asm volatile("cp.async.ca.shared.global [%0], [%1], 8;" :: "r"(dst), "l"(src));
}
__device__ __forceinline__ void cp_commit() { asm volatile("cp.async.commit_group;" ::: "memory"); }
__device__ __forceinline__ void cp_wait0()  { asm volatile("cp.async.wait_group 0;" ::: "memory"); }
__device__ __forceinline__ void cp_wait1()  { asm volatile("cp.async.wait_group 1;" ::: "memory"); }

__device__ __forceinline__ void ldm_x4(uint32_t& r0, uint32_t& r1, uint32_t& r2, uint32_t& r3,
                                       uint32_t addr) {
    asm volatile("ldmatrix.sync.aligned.m8n8.x4.shared.b16 {%0,%1,%2,%3}, [%4];"
                 : "=r"(r0), "=r"(r1), "=r"(r2), "=r"(r3) : "r"(addr));
}
__device__ __forceinline__ void mma_bf16(float* c, const uint32_t* a, const uint32_t* b) {
    asm volatile("mma.sync.aligned.m16n8k16.row.col.f32.bf16.bf16.f32 "
                 "{%0,%1,%2,%3}, {%4,%5,%6,%7}, {%8,%9}, {%0,%1,%2,%3};"
                 : "+f"(c[0]), "+f"(c[1]), "+f"(c[2]), "+f"(c[3])
                 : "r"(a[0]), "r"(a[1]), "r"(a[2]), "r"(a[3]), "r"(b[0]), "r"(b[1]));
}

// ---------------- bf16 triple-pass GEMM (unchanged from R3/R4) ----------------
#define LDS 40
#define TILEB (128 * LDS * 2)
#define STAGEB (4 * TILEB)
#define GEMM_SMEM (2 * STAGEB)

__global__ void __launch_bounds__(256, 1)
gemm3_kernel(const __nv_bfloat16* __restrict__ Ah, const __nv_bfloat16* __restrict__ Al,
             const __nv_bfloat16* __restrict__ Bh, const __nv_bfloat16* __restrict__ Bl,
             const float* __restrict__ Cadd, float* __restrict__ C, int N, int K)
{
    extern __shared__ char smem[];
    const uint32_t sb = smem_u32(smem);
    const int tid = threadIdx.x;
    const int lane = tid & 31, wid = tid >> 5;
    const int wm = wid >> 1, wn = wid & 1;
    const size_t m0 = (size_t)blockIdx.y * 128;
    const size_t n0 = (size_t)blockIdx.x * 128;
    const int KC = K >> 5;

    float acc[2][8][4];
#pragma unroll
    for (int i = 0; i < 2; i++)
#pragma unroll
        for (int j = 0; j < 8; j++)
#pragma unroll
            for (int q = 0; q < 4; q++) acc[i][j][q] = 0.f;

    const __nv_bfloat16* gbase[4] = { Ah, Al, Bh, Bl };
    const int amr = lane & 15, akc = (lane >> 4) << 3;
    const int bnr = (lane & 7) + ((lane >> 4) << 3), bkc = ((lane >> 3) & 1) << 3;

    auto load_stage = [&](int kc, int st) {
        size_t kOff = (size_t)kc << 5;
#pragma unroll
        for (int j = 0; j < 8; j++) {
            int i = tid + (j << 8);
            int t = i >> 9, r = (i >> 2) & 127, c = i & 3;
            size_t row = (t < 2) ? (m0 + r) : (n0 + r);
            const __nv_bfloat16* g = gbase[t] + row * (size_t)K + kOff + (c << 3);
            uint32_t d = sb + st * STAGEB + (uint32_t)t * TILEB + (uint32_t)(r * LDS + (c << 3)) * 2;
            cp_async16(d, g);
        }
        cp_commit();
    };

    load_stage(0, 0);

    for (int kc = 0; kc < KC; kc++) {
        int st = kc & 1;
        if (kc + 1 < KC) { load_stage(kc + 1, st ^ 1); cp_wait1(); }
        else             { cp_wait0(); }
        __syncthreads();

        uint32_t sA = sb + st * STAGEB;
        uint32_t sAh = sA;
        uint32_t sAl = sA + TILEB;
        uint32_t sBh = sA + 2 * TILEB;
        uint32_t sBl = sA + 3 * TILEB;

#pragma unroll
        for (int kk = 0; kk < 2; kk++) {
            uint32_t ah[2][4], al[2][4];
#pragma unroll
            for (int mt = 0; mt < 2; mt++) {
                uint32_t off = (uint32_t)((wm * 32 + mt * 16 + amr) * LDS + kk * 16 + akc) * 2;
                ldm_x4(ah[mt][0], ah[mt][1], ah[mt][2], ah[mt][3], sAh + off);
                ldm_x4(al[mt][0], al[mt][1], al[mt][2], al[mt][3], sAl + off);
            }
            uint32_t bh[8][2], bl[8][2];
#pragma unroll
            for (int nt2 = 0; nt2 < 4; nt2++) {
                uint32_t off = (uint32_t)((wn * 64 + nt2 * 16 + bnr) * LDS + kk * 16 + bkc) * 2;
                uint32_t r0, r1, r2, r3;
                ldm_x4(r0, r1, r2, r3, sBh + off);
                bh[nt2 * 2][0] = r0; bh[nt2 * 2][1] = r1;
                bh[nt2 * 2 + 1][0] = r2; bh[nt2 * 2 + 1][1] = r3;
                ldm_x4(r0, r1, r2, r3, sBl + off);
                bl[nt2 * 2][0] = r0; bl[nt2 * 2][1] = r1;
                bl[nt2 * 2 + 1][0] = r2; bl[nt2 * 2 + 1][1] = r3;
            }
#pragma unroll
            for (int mt = 0; mt < 2; mt++)
#pragma unroll
                for (int nt = 0; nt < 8; nt++) {
                    mma_bf16(acc[mt][nt], ah[mt], bh[nt]);
                    mma_bf16(acc[mt][nt], ah[mt], bl[nt]);
                    mma_bf16(acc[mt][nt], al[mt], bh[nt]);
                }
        }
        __syncthreads();
    }

    const int colb = (lane & 3) << 1;
    const int rowb = lane >> 2;
#pragma unroll
    for (int mt = 0; mt < 2; mt++) {
        size_t r0 = m0 + wm * 32 + mt * 16 + rowb;
#pragma unroll
        for (int half = 0; half < 2; half++) {
            size_t r = r0 + half * 8;
            float* crow = C + r * (size_t)N;
            const float* arow = Cadd ? Cadd + r * (size_t)N : nullptr;
#pragma unroll
            for (int nt = 0; nt < 8; nt++) {
                int col = (int)n0 + wn * 64 + nt * 8 + colb;
                if (col < N) {
                    float2 v;
                    v.x = acc[mt][nt][half * 2 + 0];
                    v.y = acc[mt][nt][half * 2 + 1];
                    if (arow) { v.x += arow[col]; v.y += arow[col + 1]; }
                    *(float2*)(crow + col) = v;
                }
            }
        }
    }
}

// ---------------- elementwise / norm kernels ----------------
__global__ void copy_kernel(const float* __restrict__ src, float* __restrict__ dst, size_t n4) {
    size_t i = (size_t)blockIdx.x * blockDim.x + threadIdx.x;
    if (i < n4) ((float4*)dst)[i] = ((const float4*)src)[i];
}

__global__ void rmsnorm_kernel(const float* __restrict__ src, const float* __restrict__ w,
                               float* __restrict__ dst, int D) {
    int row = blockIdx.x;
    const float* s = src + (size_t)row * D;
    float*       d = dst + (size_t)row * D;
    float ss = 0.f;
    for (int i = threadIdx.x * 4; i < D; i += blockDim.x * 4) {
        float4 v = *(const float4*)(s + i);
        ss += v.x * v.x + v.y * v.y + v.z * v.z + v.w * v.w;
    }
    float scale = rsqrtf(block_reduce_sum(ss) / (float)D + 1e-5f);
    for (int i = threadIdx.x * 4; i < D; i += blockDim.x * 4) {
        float4 v = *(const float4*)(s + i);
        float4 wv = *(const float4*)(w + i);
        float4 o;
        o.x = v.x * scale * wv.x; o.y = v.y * scale * wv.y;
        o.z = v.z * scale * wv.z; o.w = v.w * scale * wv.w;
        *(float4*)(d + i) = o;
    }
}

__global__ void rmsnorm_split_kernel(const float* __restrict__ src, const float* __restrict__ w,
                                     __nv_bfloat16* __restrict__ hi, __nv_bfloat16* __restrict__ lo,
                                     int D) {
    int row = blockIdx.x;
    const float* s = src + (size_t)row * D;
    float ss = 0.f;
    for (int i = threadIdx.x * 4; i < D; i += blockDim.x * 4) {
        float4 v = *(const float4*)(s + i);
        ss += v.x * v.x + v.y * v.y + v.z * v.z + v.w * v.w;
    }
    float scale = rsqrtf(block_reduce_sum(ss) / (float)D + 1e-5f);
    for (int i = threadIdx.x * 4; i < D; i += blockDim.x * 4) {
        float4 v = *(const float4*)(s + i);
        float4 wv = *(const float4*)(w + i);
        float o[4] = { v.x * scale * wv.x, v.y * scale * wv.y,
                       v.z * scale * wv.z, v.w * scale * wv.w };
        __nv_bfloat16 h[4], l[4];
#pragma unroll
        for (int q = 0; q < 4; q++) {
            h[q] = __float2bfloat16(o[q]);
            l[q] = __float2bfloat16(o[q] - __bfloat162float(h[q]));
        }
        *(__nv_bfloat162*)(hi + (size_t)row * D + i)     = __nv_bfloat162(h[0], h[1]);
        *(__nv_bfloat162*)(hi + (size_t)row * D + i + 2) = __nv_bfloat162(h[2], h[3]);
        *(__nv_bfloat162*)(lo + (size_t)row * D + i)     = __nv_bfloat162(l[0], l[1]);
        *(__nv_bfloat162*)(lo + (size_t)row * D + i + 2) = __nv_bfloat162(l[2], l[3]);
    }
}

__global__ void wsplit_kernel(const float* __restrict__ W,
                              __nv_bfloat16* __restrict__ Th, __nv_bfloat16* __restrict__ Tl,
                              int K, int N, int Npad) {
    __shared__ float tile[32][33];
    int nb = blockIdx.x * 32, kb = blockIdx.y * 32;
    int tx = threadIdx.x, ty = threadIdx.y;
#pragma unroll
    for (int j = 0; j < 4; j++) {
        int k = kb + ty + j * 8, n = nb + tx;
        tile[ty + j * 8][tx] = (n < N) ? W[(size_t)k * N + n] : 0.f;
    }
    __syncthreads();
#pragma unroll
    for (int j = 0; j < 4; j++) {
        int n = nb + ty + j * 8, k = kb + tx;
        float v = tile[tx][ty + j * 8];
        __nv_bfloat16 h = __float2bfloat16(v);
        Th[(size_t)n * K + k] = h;
        Tl[(size_t)n * K + k] = __float2bfloat16(v - __bfloat162float(h));
    }
}

__global__ void conv_silu_kernel(const float* __restrict__ cw, const float* __restrict__ cb) {
    size_t idx = (size_t)blockIdx.x * blockDim.x + threadIdx.x;
    if (idx >= (size_t)ROWS * CONVD) return;
    int c = (int)(idx % CONVD);
    size_t bl = idx / CONVD;
    int l = (int)(bl % SEQL);
    size_t b = bl / SEQL;
    const float* col = g_zx + (b * SEQL) * (size_t)DPROJ + DI + c;
    float w0 = cw[c * 4 + 0], w1 = cw[c * 4 + 1], w2 = cw[c * 4 + 2], w3 = cw[c * 4 + 3];
    float acc = cb[c];
    if (l >= 3) acc += col[(size_t)(l - 3) * DPROJ] * w0;
    if (l >= 2) acc += col[(size_t)(l - 2) * DPROJ] * w1;
    if (l >= 1) acc += col[(size_t)(l - 1) * DPROJ] * w2;
    acc += col[(size_t)l * DPROJ] * w3;
    g_xbc[idx] = silu_f(acc);
}

// dt = softplus(raw + bias); dA = exp(dt*A). packed as float2
__global__ void dt_kernel(const float* __restrict__ dtb, const float* __restrict__ Alog) {
    int idx = blockIdx.x * blockDim.x + threadIdx.x;
    if (idx >= ROWS * NH) return;
    int h = idx & (NH - 1);
    int bl = idx >> 6;
    float x = g_zx[(size_t)bl * DPROJ + DT_OFF + h] + dtb[h];
    float sp = (x > 20.f) ? x : log1pf(expf(x));
    g_dd[idx] = make_float2(sp, expf(sp * (-expf(Alog[h]))));
}

// ---------------- smem-staged chunked selective scan ----------------
// one CTA per (b,h); 256 threads: p = tid>>3 (headdim), sub = tid&7 (16-state chunk)
// double-buffered chunks of SCHUNK timesteps staged via cp.async
#define SCHUNK 32
#define SC_BFL (SCHUNK * 128)                 // floats per B (or C) buffer
#define SC_XFL (SCHUNK * 32)
#define SCAN_SMEM ((2 * SC_BFL * 2 + 2 * SC_XFL + 2 * SCHUNK * 2) * 4)  // 74240 B

__global__ void __launch_bounds__(256) scan_kernel(const float* __restrict__ Dv) {
    extern __shared__ float ss[];
    float* sB = ss;                            // [2][SCHUNK][128]
    float* sC = sB + 2 * SC_BFL;               // [2][SCHUNK][128]
    float* sX = sC + 2 * SC_BFL;               // [2][SCHUNK][32]
    float* sD = sX + 2 * SC_XFL;               // [2][SCHUNK] float2

    const uint32_t aB = smem_u32(sB), aC = smem_u32(sC), aX = smem_u32(sX), aD = smem_u32(sD);

    int bh = blockIdx.x;
    int b = bh >> 6, h = bh & 63;
    int tid = threadIdx.x;
    int p = tid >> 3, sub = tid & 7, n0 = sub * 16;

    float s[16];
#pragma unroll
    for (int i = 0; i < 16; i++) s[i] = 0.f;

    float Dh = Dv[h];
    const float*  xb  = g_xbc + (size_t)b * SEQL * CONVD;
    const float2* pdd = g_dd  + (size_t)b * SEQL * NH + h;
    float*        yo  = g_y   + (size_t)b * SEQL * DI + h * HP + p;

    auto load_chunk = [&](int c, int buf) {
        const float* base = xb + (size_t)c * SCHUNK * CONVD;
        // B and C: 32 rows x 512B each -> 4 x 16B chunks per thread per tensor
#pragma unroll
        for (int j = 0; j < 4; j++) {
            int i = tid + (j << 8);
            int t = i >> 5, cc = i & 31;
            const float* src = base + (size_t)t * CONVD + DI + cc * 4;
            cp_async16(aB + (uint32_t)(buf * SC_BFL + t * 128 + cc * 4) * 4, src);
            cp_async16(aC + (uint32_t)(buf * SC_BFL + t * 128 + cc * 4) * 4, src + DS);
        }
        // x: 32 rows x 128B -> 1 chunk per thread
        {
            int t = tid >> 3, cc = tid & 7;
            cp_async16(aX + (uint32_t)(buf * SC_XFL + t * 32 + cc * 4) * 4,
                       base + (size_t)t * CONVD + h * HP + cc * 4);
        }
        // dd: 32 x 8B
        if (tid < SCHUNK)
            cp_async8(aD + (uint32_t)(buf * SCHUNK + tid) * 8,
                      pdd + ((size_t)c * SCHUNK + tid) * NH);
        cp_commit();
    };

    const int NCH = SEQL / SCHUNK;
    load_chunk(0, 0);

    int buf = 0;
    for (int c = 0; c < NCH; c++) {
        if (c + 1 < NCH) { load_chunk(c + 1, buf ^ 1); cp_wait1(); }
        else             { cp_wait0(); }
        __syncthreads();

        const float*  pB = sB + buf * SC_BFL + n0;
        const float*  pC = sC + buf * SC_BFL + n0;
        const float*  pX = sX + buf * SC_XFL + p;
        const float2* pD = (const float2*)(sD + buf * SCHUNK * 2);
        size_t tg = (size_t)c * SCHUNK;

#pragma unroll 2
        for (int tt = 0; tt < SCHUNK; tt++) {
            float2 dd = pD[tt];
            float xv = pX[tt * 32];
            float Bv[16], Cv[16];
#pragma unroll
            for (int j = 0; j < 4; j++) {
                ((float4*)Bv)[j] = *(const float4*)(pB + tt * 128 + j * 4);
                ((float4*)Cv)[j] = *(const float4*)(pC + tt * 128 + j * 4);
            }
            float dtx = dd.x * xv;
            float a0 = 0.f, a1 = 0.f;
#pragma unroll
            for (int i = 0; i < 16; i += 2) {
                s[i]   = fmaf(s[i],   dd.y, dtx * Bv[i]);
                s[i+1] = fmaf(s[i+1], dd.y, dtx * Bv[i+1]);
                a0 = fmaf(s[i],   Cv[i],   a0);
                a1 = fmaf(s[i+1], Cv[i+1], a1);
            }
            float acc = a0 + a1;
            acc += __shfl_xor_sync(0xffffffffu, acc, 1);
            acc += __shfl_xor_sync(0xffffffffu, acc, 2);
            acc += __shfl_xor_sync(0xffffffffu, acc, 4);
            if (sub == 0) yo[(tg + tt) * DI] = fmaf(Dh, xv, acc);
        }
        __syncthreads();
        buf ^= 1;
    }
}

// y' = rmsnorm(y * silu(z)) * gw -> bf16 hi/lo (A operand of out_proj)
__global__ void gate_norm_split_kernel(const float* __restrict__ gw,
                                       __nv_bfloat16* __restrict__ hi,
                                       __nv_bfloat16* __restrict__ lo) {
    int row = blockIdx.x;
    const float* yr = g_y  + (size_t)row * DI;
    const float* zr = g_zx + (size_t)row * DPROJ;
    int base = threadIdx.x * 8;
    float v[8];
    float ss = 0.f;
#pragma unroll
    for (int i = 0; i < 8; i++) {
        float g = yr[base + i] * silu_f(zr[base + i]);
        v[i] = g;
        ss += g * g;
    }
    float scale = rsqrtf(block_reduce_sum(ss) / (float)DI + 1e-5f);
    __nv_bfloat16 h[8], l[8];
#pragma unroll
    for (int i = 0; i < 8; i++) {
        float o = v[i] * scale * gw[base + i];
        h[i] = __float2bfloat16(o);
        l[i] = __float2bfloat16(o - __bfloat162float(h[i]));
    }
#pragma unroll
    for (int i = 0; i < 4; i++) {
        *(__nv_bfloat162*)(hi + (size_t)row * DI + base + i * 2) = __nv_bfloat162(h[i * 2], h[i * 2 + 1]);
        *(__nv_bfloat162*)(lo + (size_t)row * DI + base + i * 2) = __nv_bfloat162(l[i * 2], l[i * 2 + 1]);
    }
}

// ---------------- launch ----------------
extern "C" void kernel_launch(void* const* d_in, const int* in_sizes, int n_in,
                              void* d_out, int out_size) {
    const float* x        = (const float*)d_in[0];
    const float* W_in     = (const float*)d_in[1];
    const float* conv_w   = (const float*)d_in[2];
    const float* conv_b   = (const float*)d_in[3];
    const float* dt_bias  = (const float*)d_in[4];
    const float* A_log    = (const float*)d_in[5];
    const float* Dvec     = (const float*)d_in[6];
    const float* gate_w   = (const float*)d_in[7];
    const float* W_out    = (const float*)d_in[8];
    const float* block_w  = (const float*)d_in[9];
    const float* final_w  = (const float*)d_in[10];

    float *ph, *pzx, *py;
    __nv_bfloat16 *pah, *pal, *pbh, *pbl;
    cudaGetSymbolAddress((void**)&ph,  g_h);
    cudaGetSymbolAddress((void**)&pzx, g_zx);
    cudaGetSymbolAddress((void**)&py,  g_y);
    cudaGetSymbolAddress((void**)&pah, g_ah);
    cudaGetSymbolAddress((void**)&pal, g_al);
    cudaGetSymbolAddress((void**)&pbh, g_bh);
    cudaGetSymbolAddress((void**)&pbl, g_bl);

    cudaFuncSetAttribute(gemm3_kernel, cudaFuncAttributeMaxDynamicSharedMemorySize, GEMM_SMEM);
    cudaFuncSetAttribute(scan_kernel, cudaFuncAttributeMaxDynamicSharedMemorySize, SCAN_SMEM);

    {
        size_t n4 = (size_t)ROWS * DM / 4;
        copy_kernel<<<(unsigned)((n4 + 255) / 256), 256>>>(x, ph, n4);
    }

    for (int l = 0; l < NL; l++) {
        rmsnorm_split_kernel<<<ROWS, 256>>>(ph, block_w + (size_t)l * DM, pah, pal, DM);
        wsplit_kernel<<<dim3(NPAD_IN / 32, DM / 32), dim3(32, 8)>>>(
            W_in + (size_t)l * DM * DPROJ, pbh, pbl, DM, DPROJ, NPAD_IN);
        gemm3_kernel<<<dim3(NPAD_IN / 128, ROWS / 128), 256, GEMM_SMEM>>>(
            pah, pal, pbh, pbl, nullptr, pzx, DPROJ, DM);

        {
            size_t n = (size_t)ROWS * CONVD;
            conv_silu_kernel<<<(unsigned)((n + 255) / 256), 256>>>(
                conv_w + (size_t)l * CONVD * DCONV, conv_b + (size_t)l * CONVD);
        }
        dt_kernel<<<(ROWS * NH + 255) / 256, 256>>>(dt_bias + (size_t)l * NH,
                                                    A_log + (size_t)l * NH);
        scan_kernel<<<BATCH * NH, 256, SCAN_SMEM>>>(Dvec + (size_t)l * NH);
        gate_norm_split_kernel<<<ROWS, 256>>>(gate_w + (size_t)l * DI, pah, pal);

        wsplit_kernel<<<dim3(DM / 32, DI / 32), dim3(32, 8)>>>(
            W_out + (size_t)l * DI * DM, pbh, pbl, DI, DM, DM);
        gemm3_kernel<<<dim3(DM / 128, ROWS / 128), 256, GEMM_SMEM>>>(
            pah, pal, pbh, pbl, ph, ph, DM, DI);
    }

    rmsnorm_kernel<<<ROWS, 256>>>(ph, final_w, (float*)d_out, DM);
}

// round 7
// speedup vs baseline: 2.8977x; 1.9554x over previous
#include <cuda_runtime.h>
#include <cuda_bf16.h>
#include <cstdint>

// ---------------- problem constants ----------------
#define BATCH   4
#define SEQL    2048
#define DM      1024
#define DI      2048
#define NH      64
#define HP      32
#define DS      128
#define DCONV   4
#define CONVD   2304            // DI + 2*DS
#define DPROJ   4416            // 2*DI + 2*DS + NH
#define NL      4
#define ROWS    (BATCH*SEQL)    // 8192
#define DT_OFF  (DI + CONVD)    // 4352
#define NPAD_IN 4480            // DPROJ padded to 128 multiple

// ---------------- device scratch (no allocation allowed) ----------------
__device__ float g_h  [(size_t)ROWS * DM];
__device__ float g_zx [(size_t)ROWS * DPROJ];
__device__ float g_xbc[(size_t)ROWS * CONVD];
__device__ float2 g_dd[(size_t)ROWS * NH];     // (dt, dA) packed
__device__ float g_y  [(size_t)ROWS * DI];
// bf16 hi/lo GEMM operands
__device__ __nv_bfloat16 g_ah[(size_t)ROWS * DI];
__device__ __nv_bfloat16 g_al[(size_t)ROWS * DI];
__device__ __nv_bfloat16 g_bh[(size_t)NPAD_IN * 1024];
__device__ __nv_bfloat16 g_bl[(size_t)NPAD_IN * 1024];

// ---------------- small helpers ----------------
__device__ __forceinline__ float silu_f(float v) { return v / (1.0f + expf(-v)); }

__device__ __forceinline__ float block_reduce_sum(float v) {
    __shared__ float red[32];
    int lane = threadIdx.x & 31, wid = threadIdx.x >> 5;
#pragma unroll
    for (int o = 16; o; o >>= 1) v += __shfl_xor_sync(0xffffffffu, v, o);
    if (lane == 0) red[wid] = v;
    __syncthreads();
    float t = (threadIdx.x < (blockDim.x >> 5)) ? red[threadIdx.x] : 0.f;
    if (wid == 0) {
#pragma unroll
        for (int o = 16; o; o >>= 1) t += __shfl_xor_sync(0xffffffffu, t, o);
        if (lane == 0) red[0] = t;
    }
    __syncthreads();
    return red[0];
}

// ---------------- PTX wrappers (sm_100-baseline safe) ----------------
__device__ __forceinline__ uint32_t smem_u32(const void* p) {
    uint32_t a;
    asm("{ .reg .u64 t; cvta.to.shared.u64 t, %1; cvt.u32.u64 %0, t; }" : "=r"(a) : "l"(p));
    return a;
}
__device__ __forceinline__ void cp_async16(uint32_t dst, const void* src) {
    asm volatile("cp.async.cg.shared.global [%0], [%1], 16;" :: "r"(dst), "l"(src));
}
__device__ __forceinline__ void cp_async8(uint32_t dst, const void* src) {
    asm volatile("cp.async.ca.shared.global [%0], [%1], 8;" :: "r"(dst), "l"(src));
}
__device__ __forceinline__ void cp_commit() { asm volatile("cp.async.commit_group;" ::: "memory"); }
__device__ __forceinline__ void cp_wait0()  { asm volatile("cp.async.wait_group 0;" ::: "memory"); }
__device__ __forceinline__ void cp_wait1()  { asm volatile("cp.async.wait_group 1;" ::: "memory"); }
__device__ __forceinline__ void cp_wait2()  { asm volatile("cp.async.wait_group 2;" ::: "memory"); }

__device__ __forceinline__ void ldm_x4(uint32_t& r0, uint32_t& r1, uint32_t& r2, uint32_t& r3,
                                       uint32_t addr) {
    asm volatile("ldmatrix.sync.aligned.m8n8.x4.shared.b16 {%0,%1,%2,%3}, [%4];"
                 : "=r"(r0), "=r"(r1), "=r"(r2), "=r"(r3) : "r"(addr));
}
__device__ __forceinline__ void mma_bf16(float* c, const uint32_t* a, const uint32_t* b) {
    asm volatile("mma.sync.aligned.m16n8k16.row.col.f32.bf16.bf16.f32 "
                 "{%0,%1,%2,%3}, {%4,%5,%6,%7}, {%8,%9}, {%0,%1,%2,%3};"
                 : "+f"(c[0]), "+f"(c[1]), "+f"(c[2]), "+f"(c[3])
                 : "r"(a[0]), "r"(a[1]), "r"(a[2]), "r"(a[3]), "r"(b[0]), "r"(b[1]));
}

// ---------------- bf16 triple-pass GEMM, 3-stage cp.async pipeline ----------------
#define LDS 40
#define TILEB (128 * LDS * 2)
#define STAGEB (4 * TILEB)
#define GEMM_SMEM (3 * STAGEB)               // 122880 B

__global__ void __launch_bounds__(256, 1)
gemm3_kernel(const __nv_bfloat16* __restrict__ Ah, const __nv_bfloat16* __restrict__ Al,
             const __nv_bfloat16* __restrict__ Bh, const __nv_bfloat16* __restrict__ Bl,
             const float* __restrict__ Cadd, float* __restrict__ C, int N, int K)
{
    extern __shared__ char smem[];
    const uint32_t sb = smem_u32(smem);
    const int tid = threadIdx.x;
    const int lane = tid & 31, wid = tid >> 5;
    const int wm = wid >> 1, wn = wid & 1;
    const size_t m0 = (size_t)blockIdx.y * 128;
    const size_t n0 = (size_t)blockIdx.x * 128;
    const int KC = K >> 5;

    float acc[2][8][4];
#pragma unroll
    for (int i = 0; i < 2; i++)
#pragma unroll
        for (int j = 0; j < 8; j++)
#pragma unroll
            for (int q = 0; q < 4; q++) acc[i][j][q] = 0.f;

    const __nv_bfloat16* gbase[4] = { Ah, Al, Bh, Bl };
    const int amr = lane & 15, akc = (lane >> 4) << 3;
    const int bnr = (lane & 7) + ((lane >> 4) << 3), bkc = ((lane >> 3) & 1) << 3;

    auto load_stage = [&](int kc, int st) {
        size_t kOff = (size_t)kc << 5;
#pragma unroll
        for (int j = 0; j < 8; j++) {
            int i = tid + (j << 8);
            int t = i >> 9, r = (i >> 2) & 127, c = i & 3;
            size_t row = (t < 2) ? (m0 + r) : (n0 + r);
            const __nv_bfloat16* g = gbase[t] + row * (size_t)K + kOff + (c << 3);
            uint32_t d = sb + st * STAGEB + (uint32_t)t * TILEB + (uint32_t)(r * LDS + (c << 3)) * 2;
            cp_async16(d, g);
        }
        cp_commit();
    };

    load_stage(0, 0);
    load_stage(1, 1);

    int st = 0;
    for (int kc = 0; kc < KC; kc++) {
        if (kc + 2 < KC) load_stage(kc + 2, (kc + 2) % 3);
        int rem = KC - 1 - kc;
        if (rem >= 2)      cp_wait2();
        else if (rem == 1) cp_wait1();
        else               cp_wait0();
        __syncthreads();

        uint32_t sA = sb + st * STAGEB;
        uint32_t sAh = sA;
        uint32_t sAl = sA + TILEB;
        uint32_t sBh = sA + 2 * TILEB;
        uint32_t sBl = sA + 3 * TILEB;

#pragma unroll
        for (int kk = 0; kk < 2; kk++) {
            uint32_t ah[2][4], al[2][4];
#pragma unroll
            for (int mt = 0; mt < 2; mt++) {
                uint32_t off = (uint32_t)((wm * 32 + mt * 16 + amr) * LDS + kk * 16 + akc) * 2;
                ldm_x4(ah[mt][0], ah[mt][1], ah[mt][2], ah[mt][3], sAh + off);
                ldm_x4(al[mt][0], al[mt][1], al[mt][2], al[mt][3], sAl + off);
            }
            uint32_t bh[8][2], bl[8][2];
#pragma unroll
            for (int nt2 = 0; nt2 < 4; nt2++) {
                uint32_t off = (uint32_t)((wn * 64 + nt2 * 16 + bnr) * LDS + kk * 16 + bkc) * 2;
                uint32_t r0, r1, r2, r3;
                ldm_x4(r0, r1, r2, r3, sBh + off);
                bh[nt2 * 2][0] = r0; bh[nt2 * 2][1] = r1;
                bh[nt2 * 2 + 1][0] = r2; bh[nt2 * 2 + 1][1] = r3;
                ldm_x4(r0, r1, r2, r3, sBl + off);
                bl[nt2 * 2][0] = r0; bl[nt2 * 2][1] = r1;
                bl[nt2 * 2 + 1][0] = r2; bl[nt2 * 2 + 1][1] = r3;
            }
#pragma unroll
            for (int mt = 0; mt < 2; mt++)
#pragma unroll
                for (int nt = 0; nt < 8; nt++) {
                    mma_bf16(acc[mt][nt], ah[mt], bh[nt]);
                    mma_bf16(acc[mt][nt], ah[mt], bl[nt]);
                    mma_bf16(acc[mt][nt], al[mt], bh[nt]);
                }
        }
        __syncthreads();
        st = (st + 1 == 3) ? 0 : st + 1;
    }

    const int colb = (lane & 3) << 1;
    const int rowb = lane >> 2;
#pragma unroll
    for (int mt = 0; mt < 2; mt++) {
        size_t r0 = m0 + wm * 32 + mt * 16 + rowb;
#pragma unroll
        for (int half = 0; half < 2; half++) {
            size_t r = r0 + half * 8;
            float* crow = C + r * (size_t)N;
            const float* arow = Cadd ? Cadd + r * (size_t)N : nullptr;
#pragma unroll
            for (int nt = 0; nt < 8; nt++) {
                int col = (int)n0 + wn * 64 + nt * 8 + colb;
                if (col < N) {
                    float2 v;
                    v.x = acc[mt][nt][half * 2 + 0];
                    v.y = acc[mt][nt][half * 2 + 1];
                    if (arow) { v.x += arow[col]; v.y += arow[col + 1]; }
                    *(float2*)(crow + col) = v;
                }
            }
        }
    }
}

// ---------------- elementwise / norm kernels ----------------
__global__ void copy_kernel(const float* __restrict__ src, float* __restrict__ dst, size_t n4) {
    size_t i = (size_t)blockIdx.x * blockDim.x + threadIdx.x;
    if (i < n4) ((float4*)dst)[i] = ((const float4*)src)[i];
}

__global__ void rmsnorm_kernel(const float* __restrict__ src, const float* __restrict__ w,
                               float* __restrict__ dst, int D) {
    int row = blockIdx.x;
    const float* s = src + (size_t)row * D;
    float*       d = dst + (size_t)row * D;
    float ss = 0.f;
    for (int i = threadIdx.x * 4; i < D; i += blockDim.x * 4) {
        float4 v = *(const float4*)(s + i);
        ss += v.x * v.x + v.y * v.y + v.z * v.z + v.w * v.w;
    }
    float scale = rsqrtf(block_reduce_sum(ss) / (float)D + 1e-5f);
    for (int i = threadIdx.x * 4; i < D; i += blockDim.x * 4) {
        float4 v = *(const float4*)(s + i);
        float4 wv = *(const float4*)(w + i);
        float4 o;
        o.x = v.x * scale * wv.x; o.y = v.y * scale * wv.y;
        o.z = v.z * scale * wv.z; o.w = v.w * scale * wv.w;
        *(float4*)(d + i) = o;
    }
}

__global__ void rmsnorm_split_kernel(const float* __restrict__ src, const float* __restrict__ w,
                                     __nv_bfloat16* __restrict__ hi, __nv_bfloat16* __restrict__ lo,
                                     int D) {
    int row = blockIdx.x;
    const float* s = src + (size_t)row * D;
    float ss = 0.f;
    for (int i = threadIdx.x * 4; i < D; i += blockDim.x * 4) {
        float4 v = *(const float4*)(s + i);
        ss += v.x * v.x + v.y * v.y + v.z * v.z + v.w * v.w;
    }
    float scale = rsqrtf(block_reduce_sum(ss) / (float)D + 1e-5f);
    for (int i = threadIdx.x * 4; i < D; i += blockDim.x * 4) {
        float4 v = *(const float4*)(s + i);
        float4 wv = *(const float4*)(w + i);
        float o[4] = { v.x * scale * wv.x, v.y * scale * wv.y,
                       v.z * scale * wv.z, v.w * scale * wv.w };
        __nv_bfloat16 h[4], l[4];
#pragma unroll
        for (int q = 0; q < 4; q++) {
            h[q] = __float2bfloat16(o[q]);
            l[q] = __float2bfloat16(o[q] - __bfloat162float(h[q]));
        }
        *(__nv_bfloat162*)(hi + (size_t)row * D + i)     = __nv_bfloat162(h[0], h[1]);
        *(__nv_bfloat162*)(hi + (size_t)row * D + i + 2) = __nv_bfloat162(h[2], h[3]);
        *(__nv_bfloat162*)(lo + (size_t)row * D + i)     = __nv_bfloat162(l[0], l[1]);
        *(__nv_bfloat162*)(lo + (size_t)row * D + i + 2) = __nv_bfloat162(l[2], l[3]);
    }
}

__global__ void wsplit_kernel(const float* __restrict__ W,
                              __nv_bfloat16* __restrict__ Th, __nv_bfloat16* __restrict__ Tl,
                              int K, int N, int Npad) {
    __shared__ float tile[32][33];
    int nb = blockIdx.x * 32, kb = blockIdx.y * 32;
    int tx = threadIdx.x, ty = threadIdx.y;
#pragma unroll
    for (int j = 0; j < 4; j++) {
        int k = kb + ty + j * 8, n = nb + tx;
        tile[ty + j * 8][tx] = (n < N) ? W[(size_t)k * N + n] : 0.f;
    }
    __syncthreads();
#pragma unroll
    for (int j = 0; j < 4; j++) {
        int n = nb + ty + j * 8, k = kb + tx;
        float v = tile[tx][ty + j * 8];
        __nv_bfloat16 h = __float2bfloat16(v);
        Th[(size_t)n * K + k] = h;
        Tl[(size_t)n * K + k] = __float2bfloat16(v - __bfloat162float(h));
    }
}

__global__ void conv_silu_kernel(const float* __restrict__ cw, const float* __restrict__ cb) {
    size_t idx = (size_t)blockIdx.x * blockDim.x + threadIdx.x;
    if (idx >= (size_t)ROWS * CONVD) return;
    int c = (int)(idx % CONVD);
    size_t bl = idx / CONVD;
    int l = (int)(bl % SEQL);
    size_t b = bl / SEQL;
    const float* col = g_zx + (b * SEQL) * (size_t)DPROJ + DI + c;
    float w0 = cw[c * 4 + 0], w1 = cw[c * 4 + 1], w2 = cw[c * 4 + 2], w3 = cw[c * 4 + 3];
    float acc = cb[c];
    if (l >= 3) acc += col[(size_t)(l - 3) * DPROJ] * w0;
    if (l >= 2) acc += col[(size_t)(l - 2) * DPROJ] * w1;
    if (l >= 1) acc += col[(size_t)(l - 1) * DPROJ] * w2;
    acc += col[(size_t)l * DPROJ] * w3;
    g_xbc[idx] = silu_f(acc);
}

// dt = softplus(raw + bias); dA = exp(dt*A). packed as float2
__global__ void dt_kernel(const float* __restrict__ dtb, const float* __restrict__ Alog) {
    int idx = blockIdx.x * blockDim.x + threadIdx.x;
    if (idx >= ROWS * NH) return;
    int h = idx & (NH - 1);
    int bl = idx >> 6;
    float x = g_zx[(size_t)bl * DPROJ + DT_OFF + h] + dtb[h];
    float sp = (x > 20.f) ? x : log1pf(expf(x));
    g_dd[idx] = make_float2(sp, expf(sp * (-expf(Alog[h]))));
}

// ---------------- selective scan: warp=n-chunk, lane=p, deferred reduction ----------
// one CTA per (b,h); 8 warps x 16 states; B/C warp-uniform broadcasts; no per-step shfl
#define SCHUNK 32
#define SC_BFL (SCHUNK * 128)                 // 4096 floats per B (or C) buffer
#define SC_XFL (SCHUNK * 32)                  // 1024
// layout: sB[2][4096] sC[2][4096] sX[2][1024] sD[2][64] sP[32*256]
#define SCAN_SMEM ((2*SC_BFL*2 + 2*SC_XFL + 2*SCHUNK*2 + SCHUNK*256) * 4)  // 107008 B

__global__ void __launch_bounds__(256) scan_kernel(const float* __restrict__ Dv) {
    extern __shared__ float ss[];
    float* sB = ss;                            // [2][SCHUNK][128]
    float* sC = sB + 2 * SC_BFL;               // [2][SCHUNK][128]
    float* sX = sC + 2 * SC_BFL;               // [2][SCHUNK][32]
    float* sD = sX + 2 * SC_XFL;               // [2][SCHUNK] float2
    float* sP = sD + 2 * SCHUNK * 2;           // [SCHUNK][256] partials

    const uint32_t aB = smem_u32(sB), aC = smem_u32(sC), aX = smem_u32(sX), aD = smem_u32(sD);

    int bh = blockIdx.x;
    int b = bh >> 6, h = bh & 63;
    int tid = threadIdx.x;
    int w = tid >> 5, lane = tid & 31;         // warp w: states n = w*16..w*16+15; lane = p

    float s[16];
#pragma unroll
    for (int i = 0; i < 16; i++) s[i] = 0.f;

    float Dh = Dv[h];
    const float*  xb  = g_xbc + (size_t)b * SEQL * CONVD;
    const float2* pdd = g_dd  + (size_t)b * SEQL * NH + h;
    float*        yb  = g_y   + (size_t)b * SEQL * DI + h * HP;

    auto load_chunk = [&](int c, int buf) {
        const float* base = xb + (size_t)c * SCHUNK * CONVD;
#pragma unroll
        for (int j = 0; j < 4; j++) {
            int i = tid + (j << 8);
            int t = i >> 5, cc = i & 31;
            const float* src = base + (size_t)t * CONVD + DI + cc * 4;
            cp_async16(aB + (uint32_t)(buf * SC_BFL + t * 128 + cc * 4) * 4, src);
            cp_async16(aC + (uint32_t)(buf * SC_BFL + t * 128 + cc * 4) * 4, src + DS);
        }
        {
            int t = tid >> 3, cc = tid & 7;
            cp_async16(aX + (uint32_t)(buf * SC_XFL + t * 32 + cc * 4) * 4,
                       base + (size_t)t * CONVD + h * HP + cc * 4);
        }
        if (tid < SCHUNK)
            cp_async8(aD + (uint32_t)(buf * SCHUNK + tid) * 8,
                      pdd + ((size_t)c * SCHUNK + tid) * NH);
        cp_commit();
    };

    const int NCH = SEQL / SCHUNK;
    load_chunk(0, 0);

    int buf = 0;
    for (int c = 0; c < NCH; c++) {
        if (c + 1 < NCH) { load_chunk(c + 1, buf ^ 1); cp_wait1(); }
        else             { cp_wait0(); }
        __syncthreads();

        const float*  pB = sB + buf * SC_BFL + w * 16;
        const float*  pC = sC + buf * SC_BFL + w * 16;
        const float*  pX = sX + buf * SC_XFL;
        const float2* pD = (const float2*)(sD + buf * SCHUNK * 2);

#pragma unroll 2
        for (int tt = 0; tt < SCHUNK; tt++) {
            float2 dd = pD[tt];                      // broadcast
            float xv = pX[tt * 32 + lane];           // conflict-free
            float Bv[16], Cv[16];
#pragma unroll
            for (int j = 0; j < 4; j++) {            // warp-uniform broadcasts
                ((float4*)Bv)[j] = *(const float4*)(pB + tt * 128 + j * 4);
                ((float4*)Cv)[j] = *(const float4*)(pC + tt * 128 + j * 4);
            }
            float dtx = dd.x * xv;
            float a0 = 0.f, a1 = 0.f;
#pragma unroll
            for (int i = 0; i < 16; i += 2) {
                s[i]   = fmaf(s[i],   dd.y, dtx * Bv[i]);
                s[i+1] = fmaf(s[i+1], dd.y, dtx * Bv[i+1]);
                a0 = fmaf(s[i],   Cv[i],   a0);
                a1 = fmaf(s[i+1], Cv[i+1], a1);
            }
            sP[tt * 256 + tid] = a0 + a1;            // conflict-free partial store
        }
        __syncthreads();

        // reduce partials: y[tt][p] = sum over 8 warps (+ D*x), coalesced store
        size_t tg = (size_t)c * SCHUNK;
#pragma unroll
        for (int q = 0; q < 4; q++) {
            int idx = q * 256 + tid;
            int tt = idx >> 5, p = idx & 31;
            const float* pp = sP + tt * 256 + p;
            float y = pp[0] + pp[32] + pp[64] + pp[96] +
                      pp[128] + pp[160] + pp[192] + pp[224];
            float xv = sX[buf * SC_XFL + tt * 32 + p];
            yb[(tg + tt) * DI + p] = fmaf(Dh, xv, y);
        }
        __syncthreads();
        buf ^= 1;
    }
}

// y' = rmsnorm(y * silu(z)) * gw -> bf16 hi/lo (A operand of out_proj)
__global__ void gate_norm_split_kernel(const float* __restrict__ gw,
                                       __nv_bfloat16* __restrict__ hi,
                                       __nv_bfloat16* __restrict__ lo) {
    int row = blockIdx.x;
    const float* yr = g_y  + (size_t)row * DI;
    const float* zr = g_zx + (size_t)row * DPROJ;
    int base = threadIdx.x * 8;
    float v[8];
    float ss = 0.f;
#pragma unroll
    for (int i = 0; i < 8; i++) {
        float g = yr[base + i] * silu_f(zr[base + i]);
        v[i] = g;
        ss += g * g;
    }
    float scale = rsqrtf(block_reduce_sum(ss) / (float)DI + 1e-5f);
    __nv_bfloat16 h[8], l[8];
#pragma unroll
    for (int i = 0; i < 8; i++) {
        float o = v[i] * scale * gw[base + i];
        h[i] = __float2bfloat16(o);
        l[i] = __float2bfloat16(o - __bfloat162float(h[i]));
    }
#pragma unroll
    for (int i = 0; i < 4; i++) {
        *(__nv_bfloat162*)(hi + (size_t)row * DI + base + i * 2) = __nv_bfloat162(h[i * 2], h[i * 2 + 1]);
        *(__nv_bfloat162*)(lo + (size_t)row * DI + base + i * 2) = __nv_bfloat162(l[i * 2], l[i * 2 + 1]);
    }
}

// ---------------- launch ----------------
extern "C" void kernel_launch(void* const* d_in, const int* in_sizes, int n_in,
                              void* d_out, int out_size) {
    const float* x        = (const float*)d_in[0];
    const float* W_in     = (const float*)d_in[1];
    const float* conv_w   = (const float*)d_in[2];
    const float* conv_b   = (const float*)d_in[3];
    const float* dt_bias  = (const float*)d_in[4];
    const float* A_log    = (const float*)d_in[5];
    const float* Dvec     = (const float*)d_in[6];
    const float* gate_w   = (const float*)d_in[7];
    const float* W_out    = (const float*)d_in[8];
    const float* block_w  = (const float*)d_in[9];
    const float* final_w  = (const float*)d_in[10];

    float *ph, *pzx, *py;
    __nv_bfloat16 *pah, *pal, *pbh, *pbl;
    cudaGetSymbolAddress((void**)&ph,  g_h);
    cudaGetSymbolAddress((void**)&pzx, g_zx);
    cudaGetSymbolAddress((void**)&py,  g_y);
    cudaGetSymbolAddress((void**)&pah, g_ah);
    cudaGetSymbolAddress((void**)&pal, g_al);
    cudaGetSymbolAddress((void**)&pbh, g_bh);
    cudaGetSymbolAddress((void**)&pbl, g_bl);

    cudaFuncSetAttribute(gemm3_kernel, cudaFuncAttributeMaxDynamicSharedMemorySize, GEMM_SMEM);
    cudaFuncSetAttribute(scan_kernel, cudaFuncAttributeMaxDynamicSharedMemorySize, SCAN_SMEM);

    {
        size_t n4 = (size_t)ROWS * DM / 4;
        copy_kernel<<<(unsigned)((n4 + 255) / 256), 256>>>(x, ph, n4);
    }

    for (int l = 0; l < NL; l++) {
        rmsnorm_split_kernel<<<ROWS, 256>>>(ph, block_w + (size_t)l * DM, pah, pal, DM);
        wsplit_kernel<<<dim3(NPAD_IN / 32, DM / 32), dim3(32, 8)>>>(
            W_in + (size_t)l * DM * DPROJ, pbh, pbl, DM, DPROJ, NPAD_IN);
        gemm3_kernel<<<dim3(NPAD_IN / 128, ROWS / 128), 256, GEMM_SMEM>>>(
            pah, pal, pbh, pbl, nullptr, pzx, DPROJ, DM);

        {
            size_t n = (size_t)ROWS * CONVD;
            conv_silu_kernel<<<(unsigned)((n + 255) / 256), 256>>>(
                conv_w + (size_t)l * CONVD * DCONV, conv_b + (size_t)l * CONVD);
        }
        dt_kernel<<<(ROWS * NH + 255) / 256, 256>>>(dt_bias + (size_t)l * NH,
                                                    A_log + (size_t)l * NH);
        scan_kernel<<<BATCH * NH, 256, SCAN_SMEM>>>(Dvec + (size_t)l * NH);
        gate_norm_split_kernel<<<ROWS, 256>>>(gate_w + (size_t)l * DI, pah, pal);

        wsplit_kernel<<<dim3(DM / 32, DI / 32), dim3(32, 8)>>>(
            W_out + (size_t)l * DI * DM, pbh, pbl, DI, DM, DM);
        gemm3_kernel<<<dim3(DM / 128, ROWS / 128), 256, GEMM_SMEM>>>(
            pah, pal, pbh, pbl, ph, ph, DM, DI);
    }

    rmsnorm_kernel<<<ROWS, 256>>>(ph, final_w, (float*)d_out, DM);
}

// round 8
// speedup vs baseline: 3.4749x; 1.1992x over previous
#include <cuda_runtime.h>
#include <cuda_bf16.h>
#include <cstdint>

// ---------------- problem constants ----------------
#define BATCH   4
#define SEQL    2048
#define DM      1024
#define DI      2048
#define NH      64
#define HP      32
#define DS      128
#define DCONV   4
#define CONVD   2304            // DI + 2*DS
#define DPROJ   4416            // 2*DI + 2*DS + NH
#define NL      4
#define ROWS    (BATCH*SEQL)    // 8192
#define DT_OFF  (DI + CONVD)    // 4352
#define NPAD_IN 4480            // DPROJ padded to 128 multiple

// ---------------- device scratch (no allocation allowed) ----------------
__device__ float g_h  [(size_t)ROWS * DM];
__device__ float g_zx [(size_t)ROWS * DPROJ];
__device__ float g_xbc[(size_t)ROWS * CONVD];
__device__ float2 g_dd[(size_t)ROWS * NH];     // (dt, dA) packed
__device__ float g_y  [(size_t)ROWS * DI];
// bf16 hi/lo GEMM operands
__device__ __nv_bfloat16 g_ah[(size_t)ROWS * DI];
__device__ __nv_bfloat16 g_al[(size_t)ROWS * DI];
__device__ __nv_bfloat16 g_bh[(size_t)NPAD_IN * 1024];
__device__ __nv_bfloat16 g_bl[(size_t)NPAD_IN * 1024];

// ---------------- small helpers ----------------
__device__ __forceinline__ float silu_f(float v) { return v / (1.0f + expf(-v)); }

__device__ __forceinline__ float block_reduce_sum(float v) {
    __shared__ float red[32];
    int lane = threadIdx.x & 31, wid = threadIdx.x >> 5;
#pragma unroll
    for (int o = 16; o; o >>= 1) v += __shfl_xor_sync(0xffffffffu, v, o);
    if (lane == 0) red[wid] = v;
    __syncthreads();
    float t = (threadIdx.x < (blockDim.x >> 5)) ? red[threadIdx.x] : 0.f;
    if (wid == 0) {
#pragma unroll
        for (int o = 16; o; o >>= 1) t += __shfl_xor_sync(0xffffffffu, t, o);
        if (lane == 0) red[0] = t;
    }
    __syncthreads();
    return red[0];
}

// ---------------- PTX wrappers (sm_100-baseline safe) ----------------
__device__ __forceinline__ uint32_t smem_u32(const void* p) {
    uint32_t a;
    asm("{ .reg .u64 t; cvta.to.shared.u64 t, %1; cvt.u32.u64 %0, t; }" : "=r"(a) : "l"(p));
    return a;
}
__device__ __forceinline__ void cp_async16(uint32_t dst, const void* src) {
    asm volatile("cp.async.cg.shared.global [%0], [%1], 16;" :: "r"(dst), "l"(src));
}
__device__ __forceinline__ void cp_async8(uint32_t dst, const void* src) {
    asm volatile("cp.async.ca.shared.global [%0], [%1], 8;" :: "r"(dst), "l"(src));
}
__device__ __forceinline__ void cp_commit() { asm volatile("cp.async.commit_group;" ::: "memory"); }
__device__ __forceinline__ void cp_wait0()  { asm volatile("cp.async.wait_group 0;" ::: "memory"); }
__device__ __forceinline__ void cp_wait1()  { asm volatile("cp.async.wait_group 1;" ::: "memory"); }

__device__ __forceinline__ void ldm_x4(uint32_t& r0, uint32_t& r1, uint32_t& r2, uint32_t& r3,
                                       uint32_t addr) {
    asm volatile("ldmatrix.sync.aligned.m8n8.x4.shared.b16 {%0,%1,%2,%3}, [%4];"
                 : "=r"(r0), "=r"(r1), "=r"(r2), "=r"(r3) : "r"(addr));
}
__device__ __forceinline__ void mma_bf16(float* c, const uint32_t* a, const uint32_t* b) {
    asm volatile("mma.sync.aligned.m16n8k16.row.col.f32.bf16.bf16.f32 "
                 "{%0,%1,%2,%3}, {%4,%5,%6,%7}, {%8,%9}, {%0,%1,%2,%3};"
                 : "+f"(c[0]), "+f"(c[1]), "+f"(c[2]), "+f"(c[3])
                 : "r"(a[0]), "r"(a[1]), "r"(a[2]), "r"(a[3]), "r"(b[0]), "r"(b[1]));
}

// ---------------- bf16 triple-pass GEMM, 2-stage, 2 CTAs/SM ----------------
#define LDS 40
#define TILEB (128 * LDS * 2)
#define STAGEB (4 * TILEB)
#define GEMM_SMEM (2 * STAGEB)               // 81920 B -> 2 CTAs/SM

__global__ void __launch_bounds__(256, 2)
gemm3_kernel(const __nv_bfloat16* __restrict__ Ah, const __nv_bfloat16* __restrict__ Al,
             const __nv_bfloat16* __restrict__ Bh, const __nv_bfloat16* __restrict__ Bl,
             const float* __restrict__ Cadd, float* __restrict__ C, int N, int K)
{
    extern __shared__ char smem[];
    const uint32_t sb = smem_u32(smem);
    const int tid = threadIdx.x;
    const int lane = tid & 31, wid = tid >> 5;
    const int wm = wid >> 1, wn = wid & 1;
    const size_t m0 = (size_t)blockIdx.y * 128;
    const size_t n0 = (size_t)blockIdx.x * 128;
    const int KC = K >> 5;

    float acc[2][8][4];
#pragma unroll
    for (int i = 0; i < 2; i++)
#pragma unroll
        for (int j = 0; j < 8; j++)
#pragma unroll
            for (int q = 0; q < 4; q++) acc[i][j][q] = 0.f;

    const __nv_bfloat16* gbase[4] = { Ah, Al, Bh, Bl };
    const int amr = lane & 15, akc = (lane >> 4) << 3;
    const int bnr = (lane & 7) + ((lane >> 4) << 3), bkc = ((lane >> 3) & 1) << 3;

    auto load_stage = [&](int kc, int st) {
        size_t kOff = (size_t)kc << 5;
#pragma unroll
        for (int j = 0; j < 8; j++) {
            int i = tid + (j << 8);
            int t = i >> 9, r = (i >> 2) & 127, c = i & 3;
            size_t row = (t < 2) ? (m0 + r) : (n0 + r);
            const __nv_bfloat16* g = gbase[t] + row * (size_t)K + kOff + (c << 3);
            uint32_t d = sb + st * STAGEB + (uint32_t)t * TILEB + (uint32_t)(r * LDS + (c << 3)) * 2;
            cp_async16(d, g);
        }
        cp_commit();
    };

    load_stage(0, 0);

    for (int kc = 0; kc < KC; kc++) {
        int st = kc & 1;
        if (kc + 1 < KC) { load_stage(kc + 1, st ^ 1); cp_wait1(); }
        else             { cp_wait0(); }
        __syncthreads();

        uint32_t sA = sb + st * STAGEB;
        uint32_t sAh = sA;
        uint32_t sAl = sA + TILEB;
        uint32_t sBh = sA + 2 * TILEB;
        uint32_t sBl = sA + 3 * TILEB;

#pragma unroll
        for (int kk = 0; kk < 2; kk++) {
            uint32_t ah[2][4], al[2][4];
#pragma unroll
            for (int mt = 0; mt < 2; mt++) {
                uint32_t off = (uint32_t)((wm * 32 + mt * 16 + amr) * LDS + kk * 16 + akc) * 2;
                ldm_x4(ah[mt][0], ah[mt][1], ah[mt][2], ah[mt][3], sAh + off);
                ldm_x4(al[mt][0], al[mt][1], al[mt][2], al[mt][3], sAl + off);
            }
            // B loaded per n16 group and consumed immediately (low live-reg count)
#pragma unroll
            for (int nt2 = 0; nt2 < 4; nt2++) {
                uint32_t off = (uint32_t)((wn * 64 + nt2 * 16 + bnr) * LDS + kk * 16 + bkc) * 2;
                uint32_t bh0[2], bh1[2], bl0[2], bl1[2];
                ldm_x4(bh0[0], bh0[1], bh1[0], bh1[1], sBh + off);
                ldm_x4(bl0[0], bl0[1], bl1[0], bl1[1], sBl + off);
#pragma unroll
                for (int mt = 0; mt < 2; mt++) {
                    mma_bf16(acc[mt][nt2 * 2],     ah[mt], bh0);
                    mma_bf16(acc[mt][nt2 * 2 + 1], ah[mt], bh1);
                    mma_bf16(acc[mt][nt2 * 2],     ah[mt], bl0);
                    mma_bf16(acc[mt][nt2 * 2 + 1], ah[mt], bl1);
                    mma_bf16(acc[mt][nt2 * 2],     al[mt], bh0);
                    mma_bf16(acc[mt][nt2 * 2 + 1], al[mt], bh1);
                }
            }
        }
        __syncthreads();
    }

    const int colb = (lane & 3) << 1;
    const int rowb = lane >> 2;
#pragma unroll
    for (int mt = 0; mt < 2; mt++) {
        size_t r0 = m0 + wm * 32 + mt * 16 + rowb;
#pragma unroll
        for (int half = 0; half < 2; half++) {
            size_t r = r0 + half * 8;
            float* crow = C + r * (size_t)N;
            const float* arow = Cadd ? Cadd + r * (size_t)N : nullptr;
#pragma unroll
            for (int nt = 0; nt < 8; nt++) {
                int col = (int)n0 + wn * 64 + nt * 8 + colb;
                if (col < N) {
                    float2 v;
                    v.x = acc[mt][nt][half * 2 + 0];
                    v.y = acc[mt][nt][half * 2 + 1];
                    if (arow) { v.x += arow[col]; v.y += arow[col + 1]; }
                    *(float2*)(crow + col) = v;
                }
            }
        }
    }
}

// ---------------- elementwise / norm kernels ----------------
__global__ void copy_kernel(const float* __restrict__ src, float* __restrict__ dst, size_t n4) {
    size_t i = (size_t)blockIdx.x * blockDim.x + threadIdx.x;
    if (i < n4) ((float4*)dst)[i] = ((const float4*)src)[i];
}

__global__ void rmsnorm_kernel(const float* __restrict__ src, const float* __restrict__ w,
                               float* __restrict__ dst, int D) {
    int row = blockIdx.x;
    const float* s = src + (size_t)row * D;
    float*       d = dst + (size_t)row * D;
    float ss = 0.f;
    for (int i = threadIdx.x * 4; i < D; i += blockDim.x * 4) {
        float4 v = *(const float4*)(s + i);
        ss += v.x * v.x + v.y * v.y + v.z * v.z + v.w * v.w;
    }
    float scale = rsqrtf(block_reduce_sum(ss) / (float)D + 1e-5f);
    for (int i = threadIdx.x * 4; i < D; i += blockDim.x * 4) {
        float4 v = *(const float4*)(s + i);
        float4 wv = *(const float4*)(w + i);
        float4 o;
        o.x = v.x * scale * wv.x; o.y = v.y * scale * wv.y;
        o.z = v.z * scale * wv.z; o.w = v.w * scale * wv.w;
        *(float4*)(d + i) = o;
    }
}

__global__ void rmsnorm_split_kernel(const float* __restrict__ src, const float* __restrict__ w,
                                     __nv_bfloat16* __restrict__ hi, __nv_bfloat16* __restrict__ lo,
                                     int D) {
    int row = blockIdx.x;
    const float* s = src + (size_t)row * D;
    float ss = 0.f;
    for (int i = threadIdx.x * 4; i < D; i += blockDim.x * 4) {
        float4 v = *(const float4*)(s + i);
        ss += v.x * v.x + v.y * v.y + v.z * v.z + v.w * v.w;
    }
    float scale = rsqrtf(block_reduce_sum(ss) / (float)D + 1e-5f);
    for (int i = threadIdx.x * 4; i < D; i += blockDim.x * 4) {
        float4 v = *(const float4*)(s + i);
        float4 wv = *(const float4*)(w + i);
        float o[4] = { v.x * scale * wv.x, v.y * scale * wv.y,
                       v.z * scale * wv.z, v.w * scale * wv.w };
        __nv_bfloat16 h[4], l[4];
#pragma unroll
        for (int q = 0; q < 4; q++) {
            h[q] = __float2bfloat16(o[q]);
            l[q] = __float2bfloat16(o[q] - __bfloat162float(h[q]));
        }
        *(__nv_bfloat162*)(hi + (size_t)row * D + i)     = __nv_bfloat162(h[0], h[1]);
        *(__nv_bfloat162*)(hi + (size_t)row * D + i + 2) = __nv_bfloat162(h[2], h[3]);
        *(__nv_bfloat162*)(lo + (size_t)row * D + i)     = __nv_bfloat162(l[0], l[1]);
        *(__nv_bfloat162*)(lo + (size_t)row * D + i + 2) = __nv_bfloat162(l[2], l[3]);
    }
}

__global__ void wsplit_kernel(const float* __restrict__ W,
                              __nv_bfloat16* __restrict__ Th, __nv_bfloat16* __restrict__ Tl,
                              int K, int N, int Npad) {
    __shared__ float tile[32][33];
    int nb = blockIdx.x * 32, kb = blockIdx.y * 32;
    int tx = threadIdx.x, ty = threadIdx.y;
#pragma unroll
    for (int j = 0; j < 4; j++) {
        int k = kb + ty + j * 8, n = nb + tx;
        tile[ty + j * 8][tx] = (n < N) ? W[(size_t)k * N + n] : 0.f;
    }
    __syncthreads();
#pragma unroll
    for (int j = 0; j < 4; j++) {
        int n = nb + ty + j * 8, k = kb + tx;
        float v = tile[tx][ty + j * 8];
        __nv_bfloat16 h = __float2bfloat16(v);
        Th[(size_t)n * K + k] = h;
        Tl[(size_t)n * K + k] = __float2bfloat16(v - __bfloat162float(h));
    }
}

// causal depthwise conv1d + SiLU, 4 timesteps per thread (sliding window)
__global__ void conv_silu_kernel(const float* __restrict__ cw, const float* __restrict__ cb) {
    size_t idx = (size_t)blockIdx.x * blockDim.x + threadIdx.x;
    if (idx >= (size_t)(ROWS / 4) * CONVD) return;
    int c = (int)(idx % CONVD);
    size_t r = idx / CONVD;
    int lb = (int)(r % (SEQL / 4));
    size_t b = r / (SEQL / 4);
    int l0 = lb * 4;
    const float* col = g_zx + ((b * SEQL + l0)) * (size_t)DPROJ + DI + c;
    float w0 = cw[c * 4 + 0], w1 = cw[c * 4 + 1], w2 = cw[c * 4 + 2], w3 = cw[c * 4 + 3];
    float cbv = cb[c];
    float v[7];
#pragma unroll
    for (int j = 0; j < 7; j++) {
        int l = l0 + j - 3;
        v[j] = (l >= 0) ? col[(ptrdiff_t)(j - 3) * DPROJ] : 0.f;
    }
    float* out = g_xbc + ((b * SEQL + l0)) * (size_t)CONVD + c;
#pragma unroll
    for (int k = 0; k < 4; k++) {
        float acc = cbv + v[k] * w0 + v[k + 1] * w1 + v[k + 2] * w2 + v[k + 3] * w3;
        out[(size_t)k * CONVD] = silu_f(acc);
    }
}

// dt = softplus(raw + bias); dA = exp(dt*A). packed as float2
__global__ void dt_kernel(const float* __restrict__ dtb, const float* __restrict__ Alog) {
    int idx = blockIdx.x * blockDim.x + threadIdx.x;
    if (idx >= ROWS * NH) return;
    int h = idx & (NH - 1);
    int bl = idx >> 6;
    float x = g_zx[(size_t)bl * DPROJ + DT_OFF + h] + dtb[h];
    float sp = (x > 20.f) ? x : log1pf(expf(x));
    g_dd[idx] = make_float2(sp, expf(sp * (-expf(Alog[h]))));
}

// ---------------- selective scan: warp=n-chunk, lane=p, deferred reduction ----------
#define SCHUNK 32
#define SC_BFL (SCHUNK * 128)
#define SC_XFL (SCHUNK * 32)
#define SCAN_SMEM ((2*SC_BFL*2 + 2*SC_XFL + 2*SCHUNK*2 + SCHUNK*256) * 4)  // 107008 B

__global__ void __launch_bounds__(256) scan_kernel(const float* __restrict__ Dv) {
    extern __shared__ float ss[];
    float* sB = ss;
    float* sC = sB + 2 * SC_BFL;
    float* sX = sC + 2 * SC_BFL;
    float* sD = sX + 2 * SC_XFL;
    float* sP = sD + 2 * SCHUNK * 2;

    const uint32_t aB = smem_u32(sB), aC = smem_u32(sC), aX = smem_u32(sX), aD = smem_u32(sD);

    int bh = blockIdx.x;
    int b = bh >> 6, h = bh & 63;
    int tid = threadIdx.x;
    int w = tid >> 5, lane = tid & 31;

    float s[16];
#pragma unroll
    for (int i = 0; i < 16; i++) s[i] = 0.f;

    float Dh = Dv[h];
    const float*  xb  = g_xbc + (size_t)b * SEQL * CONVD;
    const float2* pdd = g_dd  + (size_t)b * SEQL * NH + h;
    float*        yb  = g_y   + (size_t)b * SEQL * DI + h * HP;

    auto load_chunk = [&](int c, int buf) {
        const float* base = xb + (size_t)c * SCHUNK * CONVD;
#pragma unroll
        for (int j = 0; j < 4; j++) {
            int i = tid + (j << 8);
            int t = i >> 5, cc = i & 31;
            const float* src = base + (size_t)t * CONVD + DI + cc * 4;
            cp_async16(aB + (uint32_t)(buf * SC_BFL + t * 128 + cc * 4) * 4, src);
            cp_async16(aC + (uint32_t)(buf * SC_BFL + t * 128 + cc * 4) * 4, src + DS);
        }
        {
            int t = tid >> 3, cc = tid & 7;
            cp_async16(aX + (uint32_t)(buf * SC_XFL + t * 32 + cc * 4) * 4,
                       base + (size_t)t * CONVD + h * HP + cc * 4);
        }
        if (tid < SCHUNK)
            cp_async8(aD + (uint32_t)(buf * SCHUNK + tid) * 8,
                      pdd + ((size_t)c * SCHUNK + tid) * NH);
        cp_commit();
    };

    const int NCH = SEQL / SCHUNK;
    load_chunk(0, 0);

    int buf = 0;
    for (int c = 0; c < NCH; c++) {
        if (c + 1 < NCH) { load_chunk(c + 1, buf ^ 1); cp_wait1(); }
        else             { cp_wait0(); }
        __syncthreads();

        const float*  pB = sB + buf * SC_BFL + w * 16;
        const float*  pC = sC + buf * SC_BFL + w * 16;
        const float*  pX = sX + buf * SC_XFL;
        const float2* pD = (const float2*)(sD + buf * SCHUNK * 2);

#pragma unroll 2
        for (int tt = 0; tt < SCHUNK; tt++) {
            float2 dd = pD[tt];
            float xv = pX[tt * 32 + lane];
            float Bv[16], Cv[16];
#pragma unroll
            for (int j = 0; j < 4; j++) {
                ((float4*)Bv)[j] = *(const float4*)(pB + tt * 128 + j * 4);
                ((float4*)Cv)[j] = *(const float4*)(pC + tt * 128 + j * 4);
            }
            float dtx = dd.x * xv;
            float a0 = 0.f, a1 = 0.f;
#pragma unroll
            for (int i = 0; i < 16; i += 2) {
                s[i]   = fmaf(s[i],   dd.y, dtx * Bv[i]);
                s[i+1] = fmaf(s[i+1], dd.y, dtx * Bv[i+1]);
                a0 = fmaf(s[i],   Cv[i],   a0);
                a1 = fmaf(s[i+1], Cv[i+1], a1);
            }
            sP[tt * 256 + tid] = a0 + a1;
        }
        __syncthreads();

        size_t tg = (size_t)c * SCHUNK;
#pragma unroll
        for (int q = 0; q < 4; q++) {
            int idx = q * 256 + tid;
            int tt = idx >> 5, p = idx & 31;
            const float* pp = sP + tt * 256 + p;
            float y = pp[0] + pp[32] + pp[64] + pp[96] +
                      pp[128] + pp[160] + pp[192] + pp[224];
            float xv = sX[buf * SC_XFL + tt * 32 + p];
            yb[(tg + tt) * DI + p] = fmaf(Dh, xv, y);
        }
        __syncthreads();
        buf ^= 1;
    }
}

// y' = rmsnorm(y * silu(z)) * gw -> bf16 hi/lo (A operand of out_proj)
__global__ void gate_norm_split_kernel(const float* __restrict__ gw,
                                       __nv_bfloat16* __restrict__ hi,
                                       __nv_bfloat16* __restrict__ lo) {
    int row = blockIdx.x;
    const float* yr = g_y  + (size_t)row * DI;
    const float* zr = g_zx + (size_t)row * DPROJ;
    int base = threadIdx.x * 8;
    float v[8];
    float ss = 0.f;
#pragma unroll
    for (int i = 0; i < 8; i++) {
        float g = yr[base + i] * silu_f(zr[base + i]);
        v[i] = g;
        ss += g * g;
    }
    float scale = rsqrtf(block_reduce_sum(ss) / (float)DI + 1e-5f);
    __nv_bfloat16 h[8], l[8];
#pragma unroll
    for (int i = 0; i < 8; i++) {
        float o = v[i] * scale * gw[base + i];
        h[i] = __float2bfloat16(o);
        l[i] = __float2bfloat16(o - __bfloat162float(h[i]));
    }
#pragma unroll
    for (int i = 0; i < 4; i++) {
        *(__nv_bfloat162*)(hi + (size_t)row * DI + base + i * 2) = __nv_bfloat162(h[i * 2], h[i * 2 + 1]);
        *(__nv_bfloat162*)(lo + (size_t)row * DI + base + i * 2) = __nv_bfloat162(l[i * 2], l[i * 2 + 1]);
    }
}

// ---------------- launch ----------------
extern "C" void kernel_launch(void* const* d_in, const int* in_sizes, int n_in,
                              void* d_out, int out_size) {
    const float* x        = (const float*)d_in[0];
    const float* W_in     = (const float*)d_in[1];
    const float* conv_w   = (const float*)d_in[2];
    const float* conv_b   = (const float*)d_in[3];
    const float* dt_bias  = (const float*)d_in[4];
    const float* A_log    = (const float*)d_in[5];
    const float* Dvec     = (const float*)d_in[6];
    const float* gate_w   = (const float*)d_in[7];
    const float* W_out    = (const float*)d_in[8];
    const float* block_w  = (const float*)d_in[9];
    const float* final_w  = (const float*)d_in[10];

    float *ph, *pzx, *py;
    __nv_bfloat16 *pah, *pal, *pbh, *pbl;
    cudaGetSymbolAddress((void**)&ph,  g_h);
    cudaGetSymbolAddress((void**)&pzx, g_zx);
    cudaGetSymbolAddress((void**)&py,  g_y);
    cudaGetSymbolAddress((void**)&pah, g_ah);
    cudaGetSymbolAddress((void**)&pal, g_al);
    cudaGetSymbolAddress((void**)&pbh, g_bh);
    cudaGetSymbolAddress((void**)&pbl, g_bl);

    cudaFuncSetAttribute(gemm3_kernel, cudaFuncAttributeMaxDynamicSharedMemorySize, GEMM_SMEM);
    cudaFuncSetAttribute(scan_kernel, cudaFuncAttributeMaxDynamicSharedMemorySize, SCAN_SMEM);

    {
        size_t n4 = (size_t)ROWS * DM / 4;
        copy_kernel<<<(unsigned)((n4 + 255) / 256), 256>>>(x, ph, n4);
    }

    for (int l = 0; l < NL; l++) {
        rmsnorm_split_kernel<<<ROWS, 256>>>(ph, block_w + (size_t)l * DM, pah, pal, DM);
        wsplit_kernel<<<dim3(NPAD_IN / 32, DM / 32), dim3(32, 8)>>>(
            W_in + (size_t)l * DM * DPROJ, pbh, pbl, DM, DPROJ, NPAD_IN);
        gemm3_kernel<<<dim3(NPAD_IN / 128, ROWS / 128), 256, GEMM_SMEM>>>(
            pah, pal, pbh, pbl, nullptr, pzx, DPROJ, DM);

        {
            size_t n = (size_t)(ROWS / 4) * CONVD;
            conv_silu_kernel<<<(unsigned)((n + 255) / 256), 256>>>(
                conv_w + (size_t)l * CONVD * DCONV, conv_b + (size_t)l * CONVD);
        }
        dt_kernel<<<(ROWS * NH + 255) / 256, 256>>>(dt_bias + (size_t)l * NH,
                                                    A_log + (size_t)l * NH);
        scan_kernel<<<BATCH * NH, 256, SCAN_SMEM>>>(Dvec + (size_t)l * NH);
        gate_norm_split_kernel<<<ROWS, 256>>>(gate_w + (size_t)l * DI, pah, pal);

        wsplit_kernel<<<dim3(DM / 32, DI / 32), dim3(32, 8)>>>(
            W_out + (size_t)l * DI * DM, pbh, pbl, DI, DM, DM);
        gemm3_kernel<<<dim3(DM / 128, ROWS / 128), 256, GEMM_SMEM>>>(
            pah, pal, pbh, pbl, ph, ph, DM, DI);
    }

    rmsnorm_kernel<<<ROWS, 256>>>(ph, final_w, (float*)d_out, DM);
}